// round 6
// baseline (speedup 1.0000x reference)
#include <cuda_runtime.h>
#include <cuda_bf16.h>
#include <cstdint>

// Problem sizes (fixed by the dataset)
#define B_  32
#define S_  512
#define H_  768
#define MS_ 128
#define SL_ 8
#define M_  (B_ * S_)        // 16384 rows of X
#define NT_ 24               // partial-logit slices (12 n-blocks x 2 n-warps)

#define NEG_INF -1e30f

// Scratch (device globals: no allocation allowed)
__device__ float g_part[NT_ * M_];                 // partial logits per n-slice
__device__ float g_attn[M_];                       // softmax weights a[b,s]
__device__ float g_sacc[B_ * 6 * 8 * 128];         // weighted-sum partials
__device__ int   g_imax[2];                        // max|X|, max|W| (float bits)
__device__ int8_t Xq1[M_ * H_];                    // X int8 level 1
__device__ int8_t Xq2[M_ * H_];                    // X int8 level 2 (residual*128)
__device__ int8_t Wq1[H_ * H_];                    // W^T int8 level 1
__device__ int8_t Wq2[H_ * H_];                    // W^T int8 level 2

// ---------------------------------------------------------------------------
// helpers
// ---------------------------------------------------------------------------
__device__ __forceinline__ uint32_t smem_u32(const void* p) {
    uint32_t a;
    asm("{ .reg .u64 t; cvta.to.shared.u64 t, %1; cvt.u32.u64 %0, t; }"
        : "=r"(a) : "l"(p));
    return a;
}

#define CP_ASYNC4(dst, src) \
    asm volatile("cp.async.ca.shared.global [%0], [%1], 4;" :: "r"(dst), "l"(src))
#define CP_COMMIT() asm volatile("cp.async.commit_group;" ::: "memory")
#define CP_WAIT0()  asm volatile("cp.async.wait_group 0;" ::: "memory")

__device__ __forceinline__ void mma_s8(int* d, const uint32_t* a, const uint32_t* b) {
    asm volatile("mma.sync.aligned.m16n8k32.row.col.s32.s8.s8.s32 "
        "{%0,%1,%2,%3}, {%4,%5,%6,%7}, {%8,%9}, {%0,%1,%2,%3};"
        : "+r"(d[0]), "+r"(d[1]), "+r"(d[2]), "+r"(d[3])
        : "r"(a[0]), "r"(a[1]), "r"(a[2]), "r"(a[3]), "r"(b[0]), "r"(b[1]));
}

// fast tanh: tanh(x) = 1 - 2/(exp(2x)+1). 2 MUFU, abs err ~1e-6.
__device__ __forceinline__ float tanh_fast(float x) {
    float e = __expf(2.0f * x);
    return 1.0f - __fdividef(2.0f, e + 1.0f);
}

// ---------------------------------------------------------------------------
// Kernel p0: reset max slots
// ---------------------------------------------------------------------------
__global__ void reset_kernel() {
    if (threadIdx.x < 2) g_imax[threadIdx.x] = 0;
}

// ---------------------------------------------------------------------------
// Kernel p1: max|.| reduction (positive float bits compare as ints)
// ---------------------------------------------------------------------------
__global__ __launch_bounds__(256) void maxabs_kernel(const float* __restrict__ p,
                                                     int n4, int slot) {
    __shared__ float red[256];
    float m = 0.f;
    for (int i = blockIdx.x * 256 + threadIdx.x; i < n4; i += gridDim.x * 256) {
        float4 v = ((const float4*)p)[i];
        m = fmaxf(m, fmaxf(fmaxf(fabsf(v.x), fabsf(v.y)),
                           fmaxf(fabsf(v.z), fabsf(v.w))));
    }
    red[threadIdx.x] = m;
    __syncthreads();
    for (int o = 128; o > 0; o >>= 1) {
        if (threadIdx.x < o) red[threadIdx.x] = fmaxf(red[threadIdx.x], red[threadIdx.x + o]);
        __syncthreads();
    }
    if (threadIdx.x == 0) atomicMax(&g_imax[slot], __float_as_int(red[0]));
}

// ---------------------------------------------------------------------------
// Kernel p2: quantize X -> Xq1/Xq2 (row-major, 2-level int8)
// ---------------------------------------------------------------------------
__global__ __launch_bounds__(256) void quantx_kernel(const float* __restrict__ X) {
    float inv = __fdividef(127.f, __int_as_float(g_imax[0]));
    size_t i = (size_t)blockIdx.x * 256 + threadIdx.x;   // float4 index
    float4 v = ((const float4*)X)[i];
    float xs[4] = {v.x, v.y, v.z, v.w};
    uint32_t p1 = 0, p2 = 0;
#pragma unroll
    for (int e = 0; e < 4; e++) {
        float t = xs[e] * inv;
        int a1 = __float2int_rn(t);
        int a2 = __float2int_rn((t - (float)a1) * 128.f);
        p1 |= (uint32_t)(a1 & 0xFF) << (8 * e);
        p2 |= (uint32_t)(a2 & 0xFF) << (8 * e);
    }
    ((uint32_t*)Xq1)[i] = p1;
    ((uint32_t*)Xq2)[i] = p2;
}

// ---------------------------------------------------------------------------
// Kernel p3: transpose + quantize W -> Wq1/Wq2 (Wq[n][k] = W[k][n])
// ---------------------------------------------------------------------------
__global__ void quantw_kernel(const float* __restrict__ W) {
    __shared__ float t[32][33];
    float inv = __fdividef(127.f, __int_as_float(g_imax[1]));
    int n0 = blockIdx.x * 32, k0 = blockIdx.y * 32;
    int tx = threadIdx.x, ty = threadIdx.y;
    t[ty][tx] = W[(size_t)(k0 + ty) * H_ + n0 + tx];
    __syncthreads();
    float x = t[tx][ty] * inv;                 // W[k0+tx][n0+ty] scaled
    int a1 = __float2int_rn(x);
    int a2 = __float2int_rn((x - (float)a1) * 128.f);
    size_t o = (size_t)(n0 + ty) * H_ + k0 + tx;
    Wq1[o] = (int8_t)a1;
    Wq2[o] = (int8_t)a2;
}

// ---------------------------------------------------------------------------
// Kernel 1: out_vectors = masked segment max (or pad row S-2)
// ---------------------------------------------------------------------------
__global__ void gather_max_kernel(const float* __restrict__ X,
                                  const int* __restrict__ segments,
                                  const int* __restrict__ seg_mask,
                                  const int* __restrict__ idx_mask,
                                  float* __restrict__ out) {
    int bm = blockIdx.x;
    int b  = bm >> 7;
    int t  = threadIdx.x;

    __shared__ int sidx[SL_];
    __shared__ int svalid[SL_];
    if (t < SL_) {
        sidx[t]   = segments[bm * SL_ + t];
        svalid[t] = idx_mask[bm * SL_ + t];
    }
    __syncthreads();

    const float4* Xb = (const float4*)(X + (size_t)b * S_ * H_);
    bool ok = seg_mask[bm] != 0;

    float4 r;
    if (!ok) {
        r = Xb[(size_t)(S_ - 2) * (H_ / 4) + t];
    } else {
        r = make_float4(NEG_INF, NEG_INF, NEG_INF, NEG_INF);
#pragma unroll
        for (int sl = 0; sl < SL_; sl++) {
            if (svalid[sl]) {
                float4 v = Xb[(size_t)sidx[sl] * (H_ / 4) + t];
                r.x = fmaxf(r.x, v.x);
                r.y = fmaxf(r.y, v.y);
                r.z = fmaxf(r.z, v.z);
                r.w = fmaxf(r.w, v.w);
            }
        }
    }
    ((float4*)out)[(size_t)bm * (H_ / 4) + t] = r;
}

// ---------------------------------------------------------------------------
// Kernel 2: 2-level int8 mma.m16n8k32 GEMM + fused tanh/w_ctx epilogue
//   grid (12 n-blocks, 128 m-tiles), 256 threads (8 warps: 4m x 2n)
//   CTA tile 128x64, warp tile 32x32, BK=32 (one k32 MMA per chunk)
//   z = sA*sB*(acc_hh + acc_cross/128), acc_cross = a1*b2 + a2*b1
// ---------------------------------------------------------------------------
#define SA1 0
#define SA2 4096
#define SB1 8192
#define SB2 10240
#define QBUF 12288
#define SM_REQ (2 * QBUF)

// A fragment word (m, kq): kq = k/4 within BK=32 (0..7)
__device__ __forceinline__ uint32_t a_woff(int m, int kq) {
    int mt   = m >> 4;
    int lane = (m & 7) * 4 + (kq & 3);
    int r    = ((m >> 3) & 1) + 2 * ((kq >> 2) & 1);
    return (uint32_t)(((mt * 32 + lane) * 4 + r) * 4);
}
// B fragment word (n, kq)
__device__ __forceinline__ uint32_t b_woff(int n, int kq) {
    int nt   = n >> 3;
    int lane = (n & 7) * 4 + (kq & 3);
    int r    = (kq >> 2) & 1;
    return (uint32_t)(((nt * 32 + lane) * 2 + r) * 4);
}

__global__ __launch_bounds__(256, 2) void gemm_s8_kernel(
    const float* __restrict__ b_attn, const float* __restrict__ w_ctx) {

    extern __shared__ __align__(128) char smb[];
    uint32_t sbu = smem_u32(smb);

    int tid  = threadIdx.x;
    int wid  = tid >> 5, lane = tid & 31;
    int wm   = wid >> 1, wn = wid & 1;        // warp grid 4(m) x 2(n)
    int m0   = blockIdx.y * 128;
    int n0   = blockIdx.x * 64;

    int acc0[2][4][4];   // a1*b1
    int acc1[2][4][4];   // a1*b2 + a2*b1 (scale /128)
#pragma unroll
    for (int i = 0; i < 2; i++)
#pragma unroll
        for (int j = 0; j < 4; j++)
#pragma unroll
            for (int r = 0; r < 4; r++) { acc0[i][j][r] = 0; acc1[i][j][r] = 0; }

    auto stage_A = [&](int kt, uint32_t buf) {
#pragma unroll
        for (int p = 0; p < 4; p++) {
            int idx = tid + p * 256;           // 0..1023
            int m = idx >> 3, kq = idx & 7;
            size_t e = (size_t)(m0 + m) * H_ + kt + 4 * kq;
            uint32_t off = a_woff(m, kq);
            CP_ASYNC4(buf + SA1 + off, (const char*)(Xq1 + e));
            CP_ASYNC4(buf + SA2 + off, (const char*)(Xq2 + e));
        }
    };
    auto stage_B = [&](int kt, uint32_t buf) {
#pragma unroll
        for (int p = 0; p < 2; p++) {
            int idx = tid + p * 256;           // 0..511
            int n = idx >> 3, kq = idx & 7;
            size_t e = (size_t)(n0 + n) * H_ + kt + 4 * kq;
            uint32_t off = b_woff(n, kq);
            CP_ASYNC4(buf + SB1 + off, (const char*)(Wq1 + e));
            CP_ASYNC4(buf + SB2 + off, (const char*)(Wq2 + e));
        }
    };
    auto compute = [&](const char* buf) {
        uint32_t a1f[2][4], a2f[2][4], b1f[4][2], b2f[4][2];
#pragma unroll
        for (int mt = 0; mt < 2; mt++) {
            int gmt = wm * 2 + mt;
            uint4 v1 = *(const uint4*)(buf + SA1 + (gmt * 32 + lane) * 16);
            a1f[mt][0] = v1.x; a1f[mt][1] = v1.y; a1f[mt][2] = v1.z; a1f[mt][3] = v1.w;
            uint4 v2 = *(const uint4*)(buf + SA2 + (gmt * 32 + lane) * 16);
            a2f[mt][0] = v2.x; a2f[mt][1] = v2.y; a2f[mt][2] = v2.z; a2f[mt][3] = v2.w;
        }
#pragma unroll
        for (int nt = 0; nt < 4; nt++) {
            int gnt = wn * 4 + nt;
            uint2 w1 = *(const uint2*)(buf + SB1 + (gnt * 32 + lane) * 8);
            b1f[nt][0] = w1.x; b1f[nt][1] = w1.y;
            uint2 w2 = *(const uint2*)(buf + SB2 + (gnt * 32 + lane) * 8);
            b2f[nt][0] = w2.x; b2f[nt][1] = w2.y;
        }
#pragma unroll
        for (int mt = 0; mt < 2; mt++)
#pragma unroll
            for (int nt = 0; nt < 4; nt++) {
                mma_s8(acc0[mt][nt], a1f[mt], b1f[nt]);
                mma_s8(acc1[mt][nt], a1f[mt], b2f[nt]);
                mma_s8(acc1[mt][nt], a2f[mt], b1f[nt]);
            }
    };

    // ---- prologue: chunk 0 ----
    stage_A(0, sbu);
    stage_B(0, sbu);
    CP_COMMIT();
    CP_WAIT0();
    __syncthreads();

    // ---- mainloop: 24 chunks of K=32, double-buffered ----
    for (int c = 0; c < 24; c++) {
        const char* cur = smb + (c & 1) * QBUF;
        if (c < 23) {
            uint32_t nxt = sbu + ((c + 1) & 1) * QBUF;
            stage_A((c + 1) * 32, nxt);
            stage_B((c + 1) * 32, nxt);
            CP_COMMIT();
        }
        compute(cur);
        if (c < 23) CP_WAIT0();
        __syncthreads();
    }

    // ---- fused epilogue: partial logit = sum_n tanh(z + b) * w ----
    float sA = __int_as_float(g_imax[0]) * (1.f / 127.f);
    float sB = __int_as_float(g_imax[1]) * (1.f / 127.f);
    float sc = sA * sB;

    int q = lane & 3, g = lane >> 2;
    float bv[4][2], wv[4][2];
#pragma unroll
    for (int nt = 0; nt < 4; nt++)
#pragma unroll
        for (int c = 0; c < 2; c++) {
            int n = n0 + wn * 32 + nt * 8 + 2 * q + c;
            bv[nt][c] = b_attn[n];
            wv[nt][c] = w_ctx[n];
        }

    int slice = blockIdx.x * 2 + wn;
#pragma unroll
    for (int mt = 0; mt < 2; mt++) {
        float s0 = 0.f, s1 = 0.f;
#pragma unroll
        for (int nt = 0; nt < 4; nt++)
#pragma unroll
            for (int c = 0; c < 2; c++) {
                float z0 = sc * ((float)acc0[mt][nt][c]
                          + (float)acc1[mt][nt][c] * (1.f / 128.f));
                float z1 = sc * ((float)acc0[mt][nt][2 + c]
                          + (float)acc1[mt][nt][2 + c] * (1.f / 128.f));
                s0 += tanh_fast(z0 + bv[nt][c]) * wv[nt][c];
                s1 += tanh_fast(z1 + bv[nt][c]) * wv[nt][c];
            }
        s0 += __shfl_xor_sync(0xffffffffu, s0, 1);
        s0 += __shfl_xor_sync(0xffffffffu, s0, 2);
        s1 += __shfl_xor_sync(0xffffffffu, s1, 1);
        s1 += __shfl_xor_sync(0xffffffffu, s1, 2);
        if (q == 0) {
            int mg = m0 + wm * 32 + mt * 16 + g;
            g_part[slice * M_ + mg]     = s0;
            g_part[slice * M_ + mg + 8] = s1;
        }
    }
}

// ---------------------------------------------------------------------------
// Kernel 3a: softmax weights a[b,s] from 24 partial-logit slices
// ---------------------------------------------------------------------------
__global__ __launch_bounds__(256) void attn_weights_kernel() {
    int b = blockIdx.x, t = threadIdx.x;
    __shared__ float lg[S_];
    __shared__ float red[256];

    for (int s = t; s < S_; s += 256) {
        float v = 0.f;
#pragma unroll
        for (int nt = 0; nt < NT_; nt++) v += g_part[nt * M_ + b * S_ + s];
        lg[s] = v;
    }
    __syncthreads();

    float mx = fmaxf(lg[t], lg[t + 256]);
    red[t] = mx;
    __syncthreads();
    for (int o = 128; o > 0; o >>= 1) {
        if (t < o) red[t] = fmaxf(red[t], red[t + o]);
        __syncthreads();
    }
    mx = red[0];
    __syncthreads();

    float e0 = __expf(lg[t] - mx);
    float e1 = __expf(lg[t + 256] - mx);
    red[t] = e0 + e1;
    __syncthreads();
    for (int o = 128; o > 0; o >>= 1) {
        if (t < o) red[t] += red[t + o];
        __syncthreads();
    }
    float inv = 1.0f / red[0];

    g_attn[b * S_ + t]       = e0 * inv;
    g_attn[b * S_ + t + 256] = e1 * inv;
}

// ---------------------------------------------------------------------------
// Kernel 3b: partial weighted sums
// ---------------------------------------------------------------------------
__global__ __launch_bounds__(128) void wsum_partial_kernel(
    const float* __restrict__ X) {
    int b = blockIdx.x, hc = blockIdx.y, sc = blockIdx.z;
    int t = threadIdx.x;
    int h = hc * 128 + t;

    const float* Xp = X + (size_t)b * S_ * H_ + (size_t)sc * 64 * H_ + h;
    const float* ap = g_attn + b * S_ + sc * 64;

    float acc = 0.f;
#pragma unroll 8
    for (int s = 0; s < 64; s++)
        acc = fmaf(ap[s], Xp[(size_t)s * H_], acc);

    g_sacc[(((b * 6) + hc) * 8 + sc) * 128 + t] = acc;
}

// ---------------------------------------------------------------------------
// Kernel 3c: reduce 8 s-chunk partials -> sent_repr
// ---------------------------------------------------------------------------
__global__ __launch_bounds__(128) void wsum_reduce_kernel(float* __restrict__ sent) {
    int b = blockIdx.x, hc = blockIdx.y, t = threadIdx.x;
    const float* p = g_sacc + (((b * 6) + hc) * 8) * 128 + t;
    float acc = 0.f;
#pragma unroll
    for (int sc = 0; sc < 8; sc++) acc += p[sc * 128];
    sent[b * H_ + hc * 128 + t] = acc;
}

// ---------------------------------------------------------------------------
// launch
// ---------------------------------------------------------------------------
extern "C" void kernel_launch(void* const* d_in, const int* in_sizes, int n_in,
                              void* d_out, int out_size) {
    const float* X       = (const float*)d_in[0];
    const int* segments  = (const int*)d_in[1];
    const int* smask     = (const int*)d_in[2];
    const int* imask     = (const int*)d_in[3];
    const float* W       = (const float*)d_in[4];
    const float* b_attn  = (const float*)d_in[5];
    const float* w_ctx   = (const float*)d_in[6];

    float* out_vectors = (float*)d_out;
    float* sent        = (float*)d_out + (size_t)B_ * MS_ * H_;

    cudaFuncSetAttribute(gemm_s8_kernel,
                         cudaFuncAttributeMaxDynamicSharedMemorySize, SM_REQ);

    reset_kernel<<<1, 32>>>();
    maxabs_kernel<<<256, 256>>>(X, M_ * H_ / 4, 0);
    maxabs_kernel<<<64, 256>>>(W, H_ * H_ / 4, 1);
    quantx_kernel<<<(M_ * H_ / 4) / 256, 256>>>(X);
    quantw_kernel<<<dim3(24, 24), dim3(32, 32)>>>(W);
    gather_max_kernel<<<B_ * MS_, 192>>>(X, segments, smask, imask, out_vectors);
    gemm_s8_kernel<<<dim3(12, 128), 256, SM_REQ>>>(b_attn, w_ctx);
    attn_weights_kernel<<<B_, 256>>>();
    wsum_partial_kernel<<<dim3(B_, 6, 8), 128>>>(X);
    wsum_reduce_kernel<<<dim3(B_, 6), 128>>>(sent);
}

// round 7
// speedup vs baseline: 2.5084x; 2.5084x over previous
#include <cuda_runtime.h>
#include <cuda_bf16.h>
#include <cstdint>

// Problem sizes (fixed by the dataset)
#define B_  32
#define S_  512
#define H_  768
#define MS_ 128
#define SL_ 8
#define M_  (B_ * S_)        // 16384 rows of X
#define NT_ 24               // partial-logit slices (6 n-blocks x 4 n-warps)

#define NEG_INF -1e30f

// Scratch (device globals: no allocation allowed)
__device__ float g_part[NT_ * M_];                 // partial logits per n-slice
__device__ float g_attn[M_];                       // softmax weights a[b,s]
__device__ float g_sacc[B_ * 6 * 8 * 128];         // weighted-sum partials
// Fragment-major tiles: per (tile, chunk) 2048 words (8KB). hi/lo bf16 split.
__device__ uint4 Xfrag_hi[M_ * H_ / 8];
__device__ uint4 Xfrag_lo[M_ * H_ / 8];
__device__ uint4 Wfrag_hi[H_ * H_ / 8];
__device__ uint4 Wfrag_lo[H_ * H_ / 8];

// ---------------------------------------------------------------------------
// helpers
// ---------------------------------------------------------------------------
__device__ __forceinline__ uint32_t smem_u32(const void* p) {
    uint32_t a;
    asm("{ .reg .u64 t; cvta.to.shared.u64 t, %1; cvt.u32.u64 %0, t; }"
        : "=r"(a) : "l"(p));
    return a;
}

#define CP_ASYNC16(dst, src) \
    asm volatile("cp.async.cg.shared.global [%0], [%1], 16;" :: "r"(dst), "l"(src))
#define CP_COMMIT() asm volatile("cp.async.commit_group;" ::: "memory")
#define CP_WAIT0()  asm volatile("cp.async.wait_group 0;" ::: "memory")

__device__ __forceinline__ void mma_bf16(float* d, const uint32_t* a, const uint32_t* b) {
    asm volatile("mma.sync.aligned.m16n8k16.row.col.f32.bf16.bf16.f32 "
        "{%0,%1,%2,%3}, {%4,%5,%6,%7}, {%8,%9}, {%0,%1,%2,%3};"
        : "+f"(d[0]), "+f"(d[1]), "+f"(d[2]), "+f"(d[3])
        : "r"(a[0]), "r"(a[1]), "r"(a[2]), "r"(a[3]), "r"(b[0]), "r"(b[1]));
}

// fast tanh: tanh(x) = 1 - 2/(exp(2x)+1). 2 MUFU, abs err ~1e-6.
__device__ __forceinline__ float tanh_fast(float x) {
    float e = __expf(2.0f * x);
    return 1.0f - __fdividef(2.0f, e + 1.0f);
}

// split fp32 -> (hi, lo) bf16 packed pair helper
__device__ __forceinline__ void split2(float x0, float x1, uint32_t& hw, uint32_t& lw) {
    __nv_bfloat16 h0 = __float2bfloat16(x0);
    __nv_bfloat16 h1 = __float2bfloat16(x1);
    __nv_bfloat16 l0 = __float2bfloat16(x0 - __bfloat162float(h0));
    __nv_bfloat16 l1 = __float2bfloat16(x1 - __bfloat162float(h1));
    hw = (uint32_t)__bfloat16_as_ushort(h0) | ((uint32_t)__bfloat16_as_ushort(h1) << 16);
    lw = (uint32_t)__bfloat16_as_ushort(l0) | ((uint32_t)__bfloat16_as_ushort(l1) << 16);
}

// ---------------------------------------------------------------------------
// Fragment word layouts (word index within an 8KB tile of 2048 words)
//   A tile: 128m x 32k.  W = ((mt*2+ks)*32 + lane)*4 + r
//     mt=m>>4, ks=kp>>3 (kp=k/2), lane=(m&7)*4+(kp&3), r=((m>>3)&1)+2*((kp>>2)&1)
//   B tile: 128n x 32k.  W = ((nt*2+ks)*32 + lane)*2 + r
//     nt=n>>3, ks=kp>>3, lane=(n&7)*4+(kp&3), r=(kp>>2)&1
// ---------------------------------------------------------------------------

// Kernel 0a: X -> Xfrag_hi/lo, fragment-major tiles. grid (24 chunks, 128 mtiles)
__global__ __launch_bounds__(256) void xsplit_fm_kernel(const float* __restrict__ X) {
    __shared__ float sX[128][33];
    int c  = blockIdx.x;            // k-chunk 0..23
    int mb = blockIdx.y;            // m-tile 0..127
    int t  = threadIdx.x;

#pragma unroll
    for (int i = 0; i < 16; i++) {
        int idx = t + i * 256;      // 0..4095
        int m = idx >> 5, k = idx & 31;
        sX[m][k] = X[(size_t)(mb * 128 + m) * H_ + c * 32 + k];
    }
    __syncthreads();

    uint32_t* oh = (uint32_t*)Xfrag_hi + ((size_t)mb * 24 + c) * 2048;
    uint32_t* ol = (uint32_t*)Xfrag_lo + ((size_t)mb * 24 + c) * 2048;
#pragma unroll
    for (int p = 0; p < 8; p++) {
        int w = t + p * 256;        // 0..2047
        int r = w & 3, lane = (w >> 2) & 31, g = w >> 7;   // g = mt*2+ks
        int mt = g >> 1, ks = g & 1;
        int m  = mt * 16 + ((r & 1) << 3) + (lane >> 2);
        int kp = ks * 8 + ((r >> 1) << 2) + (lane & 3);
        uint32_t hw, lw;
        split2(sX[m][2 * kp], sX[m][2 * kp + 1], hw, lw);
        oh[w] = hw;
        ol[w] = lw;
    }
}

// Kernel 0b: W -> Wfrag_hi/lo (transposed: tiles over n). grid (24 chunks, 6 nblocks)
__global__ __launch_bounds__(256) void wsplit_fm_kernel(const float* __restrict__ W) {
    __shared__ float sW[32][129];
    int c  = blockIdx.x;            // k-chunk 0..23
    int nb = blockIdx.y;            // n-block 0..5
    int t  = threadIdx.x;

#pragma unroll
    for (int i = 0; i < 16; i++) {
        int idx = t + i * 256;      // 0..4095
        int k = idx >> 7, n = idx & 127;
        sW[k][n] = W[(size_t)(c * 32 + k) * H_ + nb * 128 + n];
    }
    __syncthreads();

    uint32_t* oh = (uint32_t*)Wfrag_hi + ((size_t)nb * 24 + c) * 2048;
    uint32_t* ol = (uint32_t*)Wfrag_lo + ((size_t)nb * 24 + c) * 2048;
#pragma unroll
    for (int p = 0; p < 8; p++) {
        int w = t + p * 256;
        int r = w & 1, lane = (w >> 1) & 31, g = w >> 6;   // g = nt*2+ks
        int nt = g >> 1, ks = g & 1;
        int n  = nt * 8 + (lane >> 2);
        int kp = ks * 8 + (r << 2) + (lane & 3);
        uint32_t hw, lw;
        split2(sW[2 * kp][n], sW[2 * kp + 1][n], hw, lw);
        oh[w] = hw;
        ol[w] = lw;
    }
}

// ---------------------------------------------------------------------------
// Kernel 1: out_vectors = masked segment max (or pad row S-2)
// ---------------------------------------------------------------------------
__global__ void gather_max_kernel(const float* __restrict__ X,
                                  const int* __restrict__ segments,
                                  const int* __restrict__ seg_mask,
                                  const int* __restrict__ idx_mask,
                                  float* __restrict__ out) {
    int bm = blockIdx.x;
    int b  = bm >> 7;
    int t  = threadIdx.x;

    __shared__ int sidx[SL_];
    __shared__ int svalid[SL_];
    if (t < SL_) {
        sidx[t]   = segments[bm * SL_ + t];
        svalid[t] = idx_mask[bm * SL_ + t];
    }
    __syncthreads();

    const float4* Xb = (const float4*)(X + (size_t)b * S_ * H_);
    bool ok = seg_mask[bm] != 0;

    float4 r;
    if (!ok) {
        r = Xb[(size_t)(S_ - 2) * (H_ / 4) + t];
    } else {
        r = make_float4(NEG_INF, NEG_INF, NEG_INF, NEG_INF);
#pragma unroll
        for (int sl = 0; sl < SL_; sl++) {
            if (svalid[sl]) {
                float4 v = Xb[(size_t)sidx[sl] * (H_ / 4) + t];
                r.x = fmaxf(r.x, v.x);
                r.y = fmaxf(r.y, v.y);
                r.z = fmaxf(r.z, v.z);
                r.w = fmaxf(r.w, v.w);
            }
        }
    }
    ((float4*)out)[(size_t)bm * (H_ / 4) + t] = r;
}

// ---------------------------------------------------------------------------
// Kernel 2: split-bf16 mma.sync GEMM + fused tanh/w_ctx epilogue
//   grid (6 n-blocks, 128 m-tiles), 256 threads (8 warps, warp tile 64x32)
//   BM=128 BN=128 BK=32, double-buffered fragment-major SMEM,
//   staging = linear 16B cp.async from pre-arranged fragment-major globals
// ---------------------------------------------------------------------------
#define SA_HI 0
#define SA_LO 8192
#define SB_HI 16384
#define SB_LO 24576
#define BUFSZ 32768
#define SM_REQ (2 * BUFSZ)

__global__ __launch_bounds__(256, 2) void gemm_mma_kernel(
    const float* __restrict__ b_attn, const float* __restrict__ w_ctx) {

    extern __shared__ __align__(128) char smb[];
    uint32_t sbu = smem_u32(smb);

    int tid  = threadIdx.x;
    int wid  = tid >> 5, lane = tid & 31;
    int wm   = wid >> 2, wn = wid & 3;        // warp grid 2(m) x 4(n)
    int n0   = blockIdx.x * 128;

    const char* gA_hi = (const char*)Xfrag_hi + (size_t)blockIdx.y * 24 * 8192;
    const char* gA_lo = (const char*)Xfrag_lo + (size_t)blockIdx.y * 24 * 8192;
    const char* gB_hi = (const char*)Wfrag_hi + (size_t)blockIdx.x * 24 * 8192;
    const char* gB_lo = (const char*)Wfrag_lo + (size_t)blockIdx.x * 24 * 8192;

    float d[4][4][4];
#pragma unroll
    for (int i = 0; i < 4; i++)
#pragma unroll
        for (int j = 0; j < 4; j++)
#pragma unroll
            for (int r = 0; r < 4; r++) d[i][j][r] = 0.f;

    // linear 16B staging: 8KB per region, 2 cp.async16/thread/region
    auto stage = [&](int c, uint32_t buf) {
        size_t tb = (size_t)c * 8192;
#pragma unroll
        for (int p = 0; p < 2; p++) {
            uint32_t off = (uint32_t)(tid + p * 256) * 16;
            CP_ASYNC16(buf + SA_HI + off, gA_hi + tb + off);
            CP_ASYNC16(buf + SA_LO + off, gA_lo + tb + off);
            CP_ASYNC16(buf + SB_HI + off, gB_hi + tb + off);
            CP_ASYNC16(buf + SB_LO + off, gB_lo + tb + off);
        }
    };
    auto compute = [&](const char* buf) {
#pragma unroll
        for (int s = 0; s < 3; s++) {
            const char* Ab = buf + (s < 2 ? SA_HI : SA_LO);
            const char* Bb = buf + (s == 1 ? SB_LO : SB_HI);
#pragma unroll
            for (int ks = 0; ks < 2; ks++) {
                uint32_t a[4][4], b[4][2];
#pragma unroll
                for (int mt = 0; mt < 4; mt++) {
                    uint4 v = *(const uint4*)(Ab +
                        ((((wm * 4 + mt) * 2 + ks) * 32 + lane) * 16));
                    a[mt][0] = v.x; a[mt][1] = v.y; a[mt][2] = v.z; a[mt][3] = v.w;
                }
#pragma unroll
                for (int nt = 0; nt < 4; nt++) {
                    uint2 v = *(const uint2*)(Bb +
                        ((((wn * 4 + nt) * 2 + ks) * 32 + lane) * 8));
                    b[nt][0] = v.x; b[nt][1] = v.y;
                }
#pragma unroll
                for (int mt = 0; mt < 4; mt++)
#pragma unroll
                    for (int nt = 0; nt < 4; nt++)
                        mma_bf16(d[mt][nt], a[mt], b[nt]);
            }
        }
    };

    // ---- prologue: chunk 0 ----
    stage(0, sbu);
    CP_COMMIT();
    CP_WAIT0();
    __syncthreads();

    // ---- mainloop: 24 chunks of K=32, double-buffered ----
    for (int c = 0; c < 24; c++) {
        const char* cur = smb + (c & 1) * BUFSZ;
        if (c < 23) {
            stage(c + 1, sbu + ((c + 1) & 1) * BUFSZ);
            CP_COMMIT();
        }
        compute(cur);
        if (c < 23) CP_WAIT0();
        __syncthreads();
    }

    // ---- fused epilogue: partial logit = sum_n tanh(z + b) * w ----
    int q = lane & 3, g = lane >> 2;
    float bv[4][2], wv[4][2];
#pragma unroll
    for (int nt = 0; nt < 4; nt++)
#pragma unroll
        for (int c = 0; c < 2; c++) {
            int n = n0 + wn * 32 + nt * 8 + 2 * q + c;
            bv[nt][c] = b_attn[n];
            wv[nt][c] = w_ctx[n];
        }

    int slice = blockIdx.x * 4 + wn;
    int m0 = blockIdx.y * 128;
#pragma unroll
    for (int mt = 0; mt < 4; mt++) {
        float s0 = 0.f, s1 = 0.f;
#pragma unroll
        for (int nt = 0; nt < 4; nt++)
#pragma unroll
            for (int c = 0; c < 2; c++) {
                s0 += tanh_fast(d[mt][nt][c]     + bv[nt][c]) * wv[nt][c];
                s1 += tanh_fast(d[mt][nt][2 + c] + bv[nt][c]) * wv[nt][c];
            }
        s0 += __shfl_xor_sync(0xffffffffu, s0, 1);
        s0 += __shfl_xor_sync(0xffffffffu, s0, 2);
        s1 += __shfl_xor_sync(0xffffffffu, s1, 1);
        s1 += __shfl_xor_sync(0xffffffffu, s1, 2);
        if (q == 0) {
            int mg = m0 + wm * 64 + mt * 16 + g;
            g_part[slice * M_ + mg]     = s0;
            g_part[slice * M_ + mg + 8] = s1;
        }
    }
}

// ---------------------------------------------------------------------------
// Kernel 3a: softmax weights a[b,s] from 24 partial-logit slices
// ---------------------------------------------------------------------------
__global__ __launch_bounds__(256) void attn_weights_kernel() {
    int b = blockIdx.x, t = threadIdx.x;
    __shared__ float lg[S_];
    __shared__ float red[256];

    for (int s = t; s < S_; s += 256) {
        float v = 0.f;
#pragma unroll
        for (int nt = 0; nt < NT_; nt++) v += g_part[nt * M_ + b * S_ + s];
        lg[s] = v;
    }
    __syncthreads();

    float mx = fmaxf(lg[t], lg[t + 256]);
    red[t] = mx;
    __syncthreads();
    for (int o = 128; o > 0; o >>= 1) {
        if (t < o) red[t] = fmaxf(red[t], red[t + o]);
        __syncthreads();
    }
    mx = red[0];
    __syncthreads();

    float e0 = __expf(lg[t] - mx);
    float e1 = __expf(lg[t + 256] - mx);
    red[t] = e0 + e1;
    __syncthreads();
    for (int o = 128; o > 0; o >>= 1) {
        if (t < o) red[t] += red[t + o];
        __syncthreads();
    }
    float inv = 1.0f / red[0];

    g_attn[b * S_ + t]       = e0 * inv;
    g_attn[b * S_ + t + 256] = e1 * inv;
}

// ---------------------------------------------------------------------------
// Kernel 3b: partial weighted sums
// ---------------------------------------------------------------------------
__global__ __launch_bounds__(128) void wsum_partial_kernel(
    const float* __restrict__ X) {
    int b = blockIdx.x, hc = blockIdx.y, sc = blockIdx.z;
    int t = threadIdx.x;
    int h = hc * 128 + t;

    const float* Xp = X + (size_t)b * S_ * H_ + (size_t)sc * 64 * H_ + h;
    const float* ap = g_attn + b * S_ + sc * 64;

    float acc = 0.f;
#pragma unroll 8
    for (int s = 0; s < 64; s++)
        acc = fmaf(ap[s], Xp[(size_t)s * H_], acc);

    g_sacc[(((b * 6) + hc) * 8 + sc) * 128 + t] = acc;
}

// ---------------------------------------------------------------------------
// Kernel 3c: reduce 8 s-chunk partials -> sent_repr
// ---------------------------------------------------------------------------
__global__ __launch_bounds__(128) void wsum_reduce_kernel(float* __restrict__ sent) {
    int b = blockIdx.x, hc = blockIdx.y, t = threadIdx.x;
    const float* p = g_sacc + (((b * 6) + hc) * 8) * 128 + t;
    float acc = 0.f;
#pragma unroll
    for (int sc = 0; sc < 8; sc++) acc += p[sc * 128];
    sent[b * H_ + hc * 128 + t] = acc;
}

// ---------------------------------------------------------------------------
// launch
// ---------------------------------------------------------------------------
extern "C" void kernel_launch(void* const* d_in, const int* in_sizes, int n_in,
                              void* d_out, int out_size) {
    const float* X       = (const float*)d_in[0];
    const int* segments  = (const int*)d_in[1];
    const int* smask     = (const int*)d_in[2];
    const int* imask     = (const int*)d_in[3];
    const float* W       = (const float*)d_in[4];
    const float* b_attn  = (const float*)d_in[5];
    const float* w_ctx   = (const float*)d_in[6];

    float* out_vectors = (float*)d_out;
    float* sent        = (float*)d_out + (size_t)B_ * MS_ * H_;

    cudaFuncSetAttribute(gemm_mma_kernel,
                         cudaFuncAttributeMaxDynamicSharedMemorySize, SM_REQ);

    wsplit_fm_kernel<<<dim3(24, 6), 256>>>(W);
    xsplit_fm_kernel<<<dim3(24, 128), 256>>>(X);
    gather_max_kernel<<<B_ * MS_, 192>>>(X, segments, smask, imask, out_vectors);
    gemm_mma_kernel<<<dim3(6, 128), 256, SM_REQ>>>(b_attn, w_ctx);
    attn_weights_kernel<<<B_, 256>>>();
    wsum_partial_kernel<<<dim3(B_, 6, 8), 128>>>(X);
    wsum_reduce_kernel<<<dim3(B_, 6), 128>>>(sent);
}

// round 8
// speedup vs baseline: 2.5529x; 1.0177x over previous
#include <cuda_runtime.h>
#include <cuda_bf16.h>
#include <cstdint>

// Problem sizes (fixed by the dataset)
#define B_  32
#define S_  512
#define H_  768
#define MS_ 128
#define SL_ 8
#define M_  (B_ * S_)        // 16384 rows of X
#define NT_ 24               // partial-logit slices (6 n-blocks x 4 n-warps)

#define NEG_INF -1e30f

// Scratch (device globals: no allocation allowed)
__device__ float g_part[NT_ * M_];                 // partial logits per n-slice
__device__ float g_attn[M_];                       // softmax weights a[b,s]
__device__ float g_sacc[B_ * 6 * 8 * 128];         // weighted-sum partials
// Fragment-major tiles: per (tile, chunk) 2048 words (8KB). hi/lo bf16 split.
__device__ uint4 Xfrag_hi[M_ * H_ / 8];
__device__ uint4 Xfrag_lo[M_ * H_ / 8];
__device__ uint4 Wfrag_hi[H_ * H_ / 8];
__device__ uint4 Wfrag_lo[H_ * H_ / 8];

// ---------------------------------------------------------------------------
// helpers
// ---------------------------------------------------------------------------
__device__ __forceinline__ uint32_t smem_u32(const void* p) {
    uint32_t a;
    asm("{ .reg .u64 t; cvta.to.shared.u64 t, %1; cvt.u32.u64 %0, t; }"
        : "=r"(a) : "l"(p));
    return a;
}

#define CP_ASYNC16(dst, src) \
    asm volatile("cp.async.cg.shared.global [%0], [%1], 16;" :: "r"(dst), "l"(src))
#define CP_COMMIT() asm volatile("cp.async.commit_group;" ::: "memory")
#define CP_WAIT0()  asm volatile("cp.async.wait_group 0;" ::: "memory")
#define CP_WAIT1()  asm volatile("cp.async.wait_group 1;" ::: "memory")

__device__ __forceinline__ void mma_bf16(float* d, const uint32_t* a, const uint32_t* b) {
    asm volatile("mma.sync.aligned.m16n8k16.row.col.f32.bf16.bf16.f32 "
        "{%0,%1,%2,%3}, {%4,%5,%6,%7}, {%8,%9}, {%0,%1,%2,%3};"
        : "+f"(d[0]), "+f"(d[1]), "+f"(d[2]), "+f"(d[3])
        : "r"(a[0]), "r"(a[1]), "r"(a[2]), "r"(a[3]), "r"(b[0]), "r"(b[1]));
}

// fast tanh: tanh(x) = 1 - 2/(exp(2x)+1). 2 MUFU, abs err ~1e-6.
__device__ __forceinline__ float tanh_fast(float x) {
    float e = __expf(2.0f * x);
    return 1.0f - __fdividef(2.0f, e + 1.0f);
}

// split fp32 -> (hi, lo) bf16 packed pair helper
__device__ __forceinline__ void split2(float x0, float x1, uint32_t& hw, uint32_t& lw) {
    __nv_bfloat16 h0 = __float2bfloat16(x0);
    __nv_bfloat16 h1 = __float2bfloat16(x1);
    __nv_bfloat16 l0 = __float2bfloat16(x0 - __bfloat162float(h0));
    __nv_bfloat16 l1 = __float2bfloat16(x1 - __bfloat162float(h1));
    hw = (uint32_t)__bfloat16_as_ushort(h0) | ((uint32_t)__bfloat16_as_ushort(h1) << 16);
    lw = (uint32_t)__bfloat16_as_ushort(l0) | ((uint32_t)__bfloat16_as_ushort(l1) << 16);
}

// ---------------------------------------------------------------------------
// Fragment word layouts (word index within an 8KB tile of 2048 words)
//   A tile: 128m x 32k.  W = ((mt*2+ks)*32 + lane)*4 + r
//   B tile: 128n x 32k.  W = ((nt*2+ks)*32 + lane)*2 + r
// ---------------------------------------------------------------------------

// Kernel 0a: X -> Xfrag_hi/lo, fragment-major tiles. grid (24 chunks, 128 mtiles)
__global__ __launch_bounds__(256) void xsplit_fm_kernel(const float* __restrict__ X) {
    __shared__ float sX[128][33];
    int c  = blockIdx.x;            // k-chunk 0..23
    int mb = blockIdx.y;            // m-tile 0..127
    int t  = threadIdx.x;

#pragma unroll
    for (int i = 0; i < 16; i++) {
        int idx = t + i * 256;      // 0..4095
        int m = idx >> 5, k = idx & 31;
        sX[m][k] = X[(size_t)(mb * 128 + m) * H_ + c * 32 + k];
    }
    __syncthreads();

    uint32_t* oh = (uint32_t*)Xfrag_hi + ((size_t)mb * 24 + c) * 2048;
    uint32_t* ol = (uint32_t*)Xfrag_lo + ((size_t)mb * 24 + c) * 2048;
#pragma unroll
    for (int p = 0; p < 8; p++) {
        int w = t + p * 256;        // 0..2047
        int r = w & 3, lane = (w >> 2) & 31, g = w >> 7;   // g = mt*2+ks
        int mt = g >> 1, ks = g & 1;
        int m  = mt * 16 + ((r & 1) << 3) + (lane >> 2);
        int kp = ks * 8 + ((r >> 1) << 2) + (lane & 3);
        uint32_t hw, lw;
        split2(sX[m][2 * kp], sX[m][2 * kp + 1], hw, lw);
        oh[w] = hw;
        ol[w] = lw;
    }
}

// Kernel 0b: W -> Wfrag_hi/lo (transposed: tiles over n). grid (24 chunks, 6 nblocks)
__global__ __launch_bounds__(256) void wsplit_fm_kernel(const float* __restrict__ W) {
    __shared__ float sW[32][129];
    int c  = blockIdx.x;            // k-chunk 0..23
    int nb = blockIdx.y;            // n-block 0..5
    int t  = threadIdx.x;

#pragma unroll
    for (int i = 0; i < 16; i++) {
        int idx = t + i * 256;      // 0..4095
        int k = idx >> 7, n = idx & 127;
        sW[k][n] = W[(size_t)(c * 32 + k) * H_ + nb * 128 + n];
    }
    __syncthreads();

    uint32_t* oh = (uint32_t*)Wfrag_hi + ((size_t)nb * 24 + c) * 2048;
    uint32_t* ol = (uint32_t*)Wfrag_lo + ((size_t)nb * 24 + c) * 2048;
#pragma unroll
    for (int p = 0; p < 8; p++) {
        int w = t + p * 256;
        int r = w & 1, lane = (w >> 1) & 31, g = w >> 6;   // g = nt*2+ks
        int nt = g >> 1, ks = g & 1;
        int n  = nt * 8 + (lane >> 2);
        int kp = ks * 8 + (r << 2) + (lane & 3);
        uint32_t hw, lw;
        split2(sW[2 * kp][n], sW[2 * kp + 1][n], hw, lw);
        oh[w] = hw;
        ol[w] = lw;
    }
}

// ---------------------------------------------------------------------------
// Kernel 1: out_vectors = masked segment max (or pad row S-2)
// ---------------------------------------------------------------------------
__global__ void gather_max_kernel(const float* __restrict__ X,
                                  const int* __restrict__ segments,
                                  const int* __restrict__ seg_mask,
                                  const int* __restrict__ idx_mask,
                                  float* __restrict__ out) {
    int bm = blockIdx.x;
    int b  = bm >> 7;
    int t  = threadIdx.x;

    __shared__ int sidx[SL_];
    __shared__ int svalid[SL_];
    if (t < SL_) {
        sidx[t]   = segments[bm * SL_ + t];
        svalid[t] = idx_mask[bm * SL_ + t];
    }
    __syncthreads();

    const float4* Xb = (const float4*)(X + (size_t)b * S_ * H_);
    bool ok = seg_mask[bm] != 0;

    float4 r;
    if (!ok) {
        r = Xb[(size_t)(S_ - 2) * (H_ / 4) + t];
    } else {
        r = make_float4(NEG_INF, NEG_INF, NEG_INF, NEG_INF);
#pragma unroll
        for (int sl = 0; sl < SL_; sl++) {
            if (svalid[sl]) {
                float4 v = Xb[(size_t)sidx[sl] * (H_ / 4) + t];
                r.x = fmaxf(r.x, v.x);
                r.y = fmaxf(r.y, v.y);
                r.z = fmaxf(r.z, v.z);
                r.w = fmaxf(r.w, v.w);
            }
        }
    }
    ((float4*)out)[(size_t)bm * (H_ / 4) + t] = r;
}

// ---------------------------------------------------------------------------
// Kernel 2: split-bf16 mma.sync GEMM + fused tanh/w_ctx epilogue
//   grid (6 n-blocks, 128 m-tiles), 256 threads (8 warps, warp tile 64x32)
//   BM=128 BN=128 BK=32, 3-stage cp.async pipeline (wait_group 1),
//   staging = linear 16B cp.async from pre-arranged fragment-major globals
// ---------------------------------------------------------------------------
#define SA_HI 0
#define SA_LO 8192
#define SB_HI 16384
#define SB_LO 24576
#define BUFSZ 32768
#define STAGES 3
#define SM_REQ (STAGES * BUFSZ)

__global__ __launch_bounds__(256, 2) void gemm_mma_kernel(
    const float* __restrict__ b_attn, const float* __restrict__ w_ctx) {

    extern __shared__ __align__(128) char smb[];
    uint32_t sbu = smem_u32(smb);

    int tid  = threadIdx.x;
    int wid  = tid >> 5, lane = tid & 31;
    int wm   = wid >> 2, wn = wid & 3;        // warp grid 2(m) x 4(n)
    int n0   = blockIdx.x * 128;

    const char* gA_hi = (const char*)Xfrag_hi + (size_t)blockIdx.y * 24 * 8192;
    const char* gA_lo = (const char*)Xfrag_lo + (size_t)blockIdx.y * 24 * 8192;
    const char* gB_hi = (const char*)Wfrag_hi + (size_t)blockIdx.x * 24 * 8192;
    const char* gB_lo = (const char*)Wfrag_lo + (size_t)blockIdx.x * 24 * 8192;

    float d[4][4][4];
#pragma unroll
    for (int i = 0; i < 4; i++)
#pragma unroll
        for (int j = 0; j < 4; j++)
#pragma unroll
            for (int r = 0; r < 4; r++) d[i][j][r] = 0.f;

    // linear 16B staging: 8KB per region, 2 cp.async16/thread/region
    auto stage = [&](int c, uint32_t buf) {
        size_t tb = (size_t)c * 8192;
#pragma unroll
        for (int p = 0; p < 2; p++) {
            uint32_t off = (uint32_t)(tid + p * 256) * 16;
            CP_ASYNC16(buf + SA_HI + off, gA_hi + tb + off);
            CP_ASYNC16(buf + SA_LO + off, gA_lo + tb + off);
            CP_ASYNC16(buf + SB_HI + off, gB_hi + tb + off);
            CP_ASYNC16(buf + SB_LO + off, gB_lo + tb + off);
        }
    };
    auto compute = [&](const char* buf) {
#pragma unroll
        for (int s = 0; s < 3; s++) {
            const char* Ab = buf + (s < 2 ? SA_HI : SA_LO);
            const char* Bb = buf + (s == 1 ? SB_LO : SB_HI);
#pragma unroll
            for (int ks = 0; ks < 2; ks++) {
                uint32_t a[4][4], b[4][2];
#pragma unroll
                for (int mt = 0; mt < 4; mt++) {
                    uint4 v = *(const uint4*)(Ab +
                        ((((wm * 4 + mt) * 2 + ks) * 32 + lane) * 16));
                    a[mt][0] = v.x; a[mt][1] = v.y; a[mt][2] = v.z; a[mt][3] = v.w;
                }
#pragma unroll
                for (int nt = 0; nt < 4; nt++) {
                    uint2 v = *(const uint2*)(Bb +
                        ((((wn * 4 + nt) * 2 + ks) * 32 + lane) * 8));
                    b[nt][0] = v.x; b[nt][1] = v.y;
                }
#pragma unroll
                for (int mt = 0; mt < 4; mt++)
#pragma unroll
                    for (int nt = 0; nt < 4; nt++)
                        mma_bf16(d[mt][nt], a[mt], b[nt]);
            }
        }
    };

    // ---- prologue: stages 0 and 1 in flight ----
    stage(0, sbu);
    CP_COMMIT();
    stage(1, sbu + BUFSZ);
    CP_COMMIT();

    // ---- mainloop: 24 chunks of K=32, 3-stage pipeline ----
    for (int c = 0; c < 24; c++) {
        if (c == 23) CP_WAIT0(); else CP_WAIT1();   // oldest group (c) done
        __syncthreads();
        compute(smb + (c % STAGES) * BUFSZ);
        if (c + 2 < 24) {
            stage(c + 2, sbu + ((c + 2) % STAGES) * BUFSZ);
            CP_COMMIT();
        }
    }

    // ---- fused epilogue: partial logit = sum_n tanh(z + b) * w ----
    int q = lane & 3, g = lane >> 2;
    float bv[4][2], wv[4][2];
#pragma unroll
    for (int nt = 0; nt < 4; nt++)
#pragma unroll
        for (int c = 0; c < 2; c++) {
            int n = n0 + wn * 32 + nt * 8 + 2 * q + c;
            bv[nt][c] = b_attn[n];
            wv[nt][c] = w_ctx[n];
        }

    int slice = blockIdx.x * 4 + wn;
    int m0 = blockIdx.y * 128;
#pragma unroll
    for (int mt = 0; mt < 4; mt++) {
        float s0 = 0.f, s1 = 0.f;
#pragma unroll
        for (int nt = 0; nt < 4; nt++)
#pragma unroll
            for (int c = 0; c < 2; c++) {
                s0 += tanh_fast(d[mt][nt][c]     + bv[nt][c]) * wv[nt][c];
                s1 += tanh_fast(d[mt][nt][2 + c] + bv[nt][c]) * wv[nt][c];
            }
        s0 += __shfl_xor_sync(0xffffffffu, s0, 1);
        s0 += __shfl_xor_sync(0xffffffffu, s0, 2);
        s1 += __shfl_xor_sync(0xffffffffu, s1, 1);
        s1 += __shfl_xor_sync(0xffffffffu, s1, 2);
        if (q == 0) {
            int mg = m0 + wm * 64 + mt * 16 + g;
            g_part[slice * M_ + mg]     = s0;
            g_part[slice * M_ + mg + 8] = s1;
        }
    }
}

// ---------------------------------------------------------------------------
// Kernel 3a: softmax weights a[b,s] from 24 partial-logit slices
// ---------------------------------------------------------------------------
__global__ __launch_bounds__(256) void attn_weights_kernel() {
    int b = blockIdx.x, t = threadIdx.x;
    __shared__ float lg[S_];
    __shared__ float red[256];

    for (int s = t; s < S_; s += 256) {
        float v = 0.f;
#pragma unroll
        for (int nt = 0; nt < NT_; nt++) v += g_part[nt * M_ + b * S_ + s];
        lg[s] = v;
    }
    __syncthreads();

    float mx = fmaxf(lg[t], lg[t + 256]);
    red[t] = mx;
    __syncthreads();
    for (int o = 128; o > 0; o >>= 1) {
        if (t < o) red[t] = fmaxf(red[t], red[t + o]);
        __syncthreads();
    }
    mx = red[0];
    __syncthreads();

    float e0 = __expf(lg[t] - mx);
    float e1 = __expf(lg[t + 256] - mx);
    red[t] = e0 + e1;
    __syncthreads();
    for (int o = 128; o > 0; o >>= 1) {
        if (t < o) red[t] += red[t + o];
        __syncthreads();
    }
    float inv = 1.0f / red[0];

    g_attn[b * S_ + t]       = e0 * inv;
    g_attn[b * S_ + t + 256] = e1 * inv;
}

// ---------------------------------------------------------------------------
// Kernel 3b: partial weighted sums
// ---------------------------------------------------------------------------
__global__ __launch_bounds__(128) void wsum_partial_kernel(
    const float* __restrict__ X) {
    int b = blockIdx.x, hc = blockIdx.y, sc = blockIdx.z;
    int t = threadIdx.x;
    int h = hc * 128 + t;

    const float* Xp = X + (size_t)b * S_ * H_ + (size_t)sc * 64 * H_ + h;
    const float* ap = g_attn + b * S_ + sc * 64;

    float acc = 0.f;
#pragma unroll 8
    for (int s = 0; s < 64; s++)
        acc = fmaf(ap[s], Xp[(size_t)s * H_], acc);

    g_sacc[(((b * 6) + hc) * 8 + sc) * 128 + t] = acc;
}

// ---------------------------------------------------------------------------
// Kernel 3c: reduce 8 s-chunk partials -> sent_repr
// ---------------------------------------------------------------------------
__global__ __launch_bounds__(128) void wsum_reduce_kernel(float* __restrict__ sent) {
    int b = blockIdx.x, hc = blockIdx.y, t = threadIdx.x;
    const float* p = g_sacc + (((b * 6) + hc) * 8) * 128 + t;
    float acc = 0.f;
#pragma unroll
    for (int sc = 0; sc < 8; sc++) acc += p[sc * 128];
    sent[b * H_ + hc * 128 + t] = acc;
}

// ---------------------------------------------------------------------------
// launch
// ---------------------------------------------------------------------------
extern "C" void kernel_launch(void* const* d_in, const int* in_sizes, int n_in,
                              void* d_out, int out_size) {
    const float* X       = (const float*)d_in[0];
    const int* segments  = (const int*)d_in[1];
    const int* smask     = (const int*)d_in[2];
    const int* imask     = (const int*)d_in[3];
    const float* W       = (const float*)d_in[4];
    const float* b_attn  = (const float*)d_in[5];
    const float* w_ctx   = (const float*)d_in[6];

    float* out_vectors = (float*)d_out;
    float* sent        = (float*)d_out + (size_t)B_ * MS_ * H_;

    cudaFuncSetAttribute(gemm_mma_kernel,
                         cudaFuncAttributeMaxDynamicSharedMemorySize, SM_REQ);

    wsplit_fm_kernel<<<dim3(24, 6), 256>>>(W);
    xsplit_fm_kernel<<<dim3(24, 128), 256>>>(X);
    gather_max_kernel<<<B_ * MS_, 192>>>(X, segments, smask, imask, out_vectors);
    gemm_mma_kernel<<<dim3(6, 128), 256, SM_REQ>>>(b_attn, w_ctx);
    attn_weights_kernel<<<B_, 256>>>();
    wsum_partial_kernel<<<dim3(B_, 6, 8), 128>>>(X);
    wsum_reduce_kernel<<<dim3(B_, 6), 128>>>(sent);
}

// round 9
// speedup vs baseline: 2.6195x; 1.0261x over previous
#include <cuda_runtime.h>
#include <cuda_bf16.h>
#include <cstdint>

// Problem sizes (fixed by the dataset)
#define B_  32
#define S_  512
#define H_  768
#define MS_ 128
#define SL_ 8
#define M_  (B_ * S_)        // 16384 rows of X
#define NT_ 24               // partial-logit slices (6 n-blocks x 4 n-warps)

#define NEG_INF -1e30f

// Scratch (device globals: no allocation allowed)
__device__ float g_part[NT_ * M_];                 // partial logits per n-slice
__device__ float g_attn[M_];                       // softmax weights a[b,s]
__device__ float g_sacc[B_ * 6 * 8 * 128];         // weighted-sum partials
// Fragment-major tiles: per (tile, chunk) 2048 words (8KB). hi/lo bf16 split.
__device__ uint4 Xfrag_hi[M_ * H_ / 8];
__device__ uint4 Xfrag_lo[M_ * H_ / 8];
__device__ uint4 Wfrag_hi[H_ * H_ / 8];
__device__ uint4 Wfrag_lo[H_ * H_ / 8];

// ---------------------------------------------------------------------------
// helpers
// ---------------------------------------------------------------------------
__device__ __forceinline__ uint32_t smem_u32(const void* p) {
    uint32_t a;
    asm("{ .reg .u64 t; cvta.to.shared.u64 t, %1; cvt.u32.u64 %0, t; }"
        : "=r"(a) : "l"(p));
    return a;
}

#define CP_ASYNC16(dst, src) \
    asm volatile("cp.async.cg.shared.global [%0], [%1], 16;" :: "r"(dst), "l"(src))
#define CP_COMMIT() asm volatile("cp.async.commit_group;" ::: "memory")
#define CP_WAIT0()  asm volatile("cp.async.wait_group 0;" ::: "memory")
#define CP_WAIT1()  asm volatile("cp.async.wait_group 1;" ::: "memory")

__device__ __forceinline__ void mma_bf16(float* d, const uint32_t* a, const uint32_t* b) {
    asm volatile("mma.sync.aligned.m16n8k16.row.col.f32.bf16.bf16.f32 "
        "{%0,%1,%2,%3}, {%4,%5,%6,%7}, {%8,%9}, {%0,%1,%2,%3};"
        : "+f"(d[0]), "+f"(d[1]), "+f"(d[2]), "+f"(d[3])
        : "r"(a[0]), "r"(a[1]), "r"(a[2]), "r"(a[3]), "r"(b[0]), "r"(b[1]));
}

// fast tanh: tanh(x) = 1 - 2/(exp(2x)+1). 2 MUFU, abs err ~1e-6.
__device__ __forceinline__ float tanh_fast(float x) {
    float e = __expf(2.0f * x);
    return 1.0f - __fdividef(2.0f, e + 1.0f);
}

// split fp32 -> (hi, lo) bf16 packed pair helper
__device__ __forceinline__ void split2(float x0, float x1, uint32_t& hw, uint32_t& lw) {
    __nv_bfloat16 h0 = __float2bfloat16(x0);
    __nv_bfloat16 h1 = __float2bfloat16(x1);
    __nv_bfloat16 l0 = __float2bfloat16(x0 - __bfloat162float(h0));
    __nv_bfloat16 l1 = __float2bfloat16(x1 - __bfloat162float(h1));
    hw = (uint32_t)__bfloat16_as_ushort(h0) | ((uint32_t)__bfloat16_as_ushort(h1) << 16);
    lw = (uint32_t)__bfloat16_as_ushort(l0) | ((uint32_t)__bfloat16_as_ushort(l1) << 16);
}

// ---------------------------------------------------------------------------
// Fragment word layouts (word index within an 8KB tile of 2048 words)
//   A tile: 128m x 32k.  W = ((mt*2+ks)*32 + lane)*4 + r
//   B tile: 128n x 32k.  W = ((nt*2+ks)*32 + lane)*2 + r
// ---------------------------------------------------------------------------

// Kernel 0a: X -> Xfrag_hi/lo, fragment-major tiles. grid (24 chunks, 128 mtiles)
__global__ __launch_bounds__(256) void xsplit_fm_kernel(const float* __restrict__ X) {
    __shared__ float sX[128][33];
    int c  = blockIdx.x;            // k-chunk 0..23
    int mb = blockIdx.y;            // m-tile 0..127
    int t  = threadIdx.x;

#pragma unroll
    for (int i = 0; i < 16; i++) {
        int idx = t + i * 256;      // 0..4095
        int m = idx >> 5, k = idx & 31;
        sX[m][k] = X[(size_t)(mb * 128 + m) * H_ + c * 32 + k];
    }
    __syncthreads();

    uint32_t* oh = (uint32_t*)Xfrag_hi + ((size_t)mb * 24 + c) * 2048;
    uint32_t* ol = (uint32_t*)Xfrag_lo + ((size_t)mb * 24 + c) * 2048;
#pragma unroll
    for (int p = 0; p < 8; p++) {
        int w = t + p * 256;        // 0..2047
        int r = w & 3, lane = (w >> 2) & 31, g = w >> 7;   // g = mt*2+ks
        int mt = g >> 1, ks = g & 1;
        int m  = mt * 16 + ((r & 1) << 3) + (lane >> 2);
        int kp = ks * 8 + ((r >> 1) << 2) + (lane & 3);
        uint32_t hw, lw;
        split2(sX[m][2 * kp], sX[m][2 * kp + 1], hw, lw);
        oh[w] = hw;
        ol[w] = lw;
    }
}

// Kernel 0b: W -> Wfrag_hi/lo (transposed: tiles over n). grid (24 chunks, 6 nblocks)
__global__ __launch_bounds__(256) void wsplit_fm_kernel(const float* __restrict__ W) {
    __shared__ float sW[32][129];
    int c  = blockIdx.x;            // k-chunk 0..23
    int nb = blockIdx.y;            // n-block 0..5
    int t  = threadIdx.x;

#pragma unroll
    for (int i = 0; i < 16; i++) {
        int idx = t + i * 256;      // 0..4095
        int k = idx >> 7, n = idx & 127;
        sW[k][n] = W[(size_t)(c * 32 + k) * H_ + nb * 128 + n];
    }
    __syncthreads();

    uint32_t* oh = (uint32_t*)Wfrag_hi + ((size_t)nb * 24 + c) * 2048;
    uint32_t* ol = (uint32_t*)Wfrag_lo + ((size_t)nb * 24 + c) * 2048;
#pragma unroll
    for (int p = 0; p < 8; p++) {
        int w = t + p * 256;
        int r = w & 1, lane = (w >> 1) & 31, g = w >> 6;   // g = nt*2+ks
        int nt = g >> 1, ks = g & 1;
        int n  = nt * 8 + (lane >> 2);
        int kp = ks * 8 + (r << 2) + (lane & 3);
        uint32_t hw, lw;
        split2(sW[2 * kp][n], sW[2 * kp + 1][n], hw, lw);
        oh[w] = hw;
        ol[w] = lw;
    }
}

// ---------------------------------------------------------------------------
// Kernel 1: out_vectors = masked segment max (or pad row S-2)
// ---------------------------------------------------------------------------
__global__ void gather_max_kernel(const float* __restrict__ X,
                                  const int* __restrict__ segments,
                                  const int* __restrict__ seg_mask,
                                  const int* __restrict__ idx_mask,
                                  float* __restrict__ out) {
    int bm = blockIdx.x;
    int b  = bm >> 7;
    int t  = threadIdx.x;

    __shared__ int sidx[SL_];
    __shared__ int svalid[SL_];
    if (t < SL_) {
        sidx[t]   = segments[bm * SL_ + t];
        svalid[t] = idx_mask[bm * SL_ + t];
    }
    __syncthreads();

    const float4* Xb = (const float4*)(X + (size_t)b * S_ * H_);
    bool ok = seg_mask[bm] != 0;

    float4 r;
    if (!ok) {
        r = Xb[(size_t)(S_ - 2) * (H_ / 4) + t];
    } else {
        r = make_float4(NEG_INF, NEG_INF, NEG_INF, NEG_INF);
#pragma unroll
        for (int sl = 0; sl < SL_; sl++) {
            if (svalid[sl]) {
                float4 v = Xb[(size_t)sidx[sl] * (H_ / 4) + t];
                r.x = fmaxf(r.x, v.x);
                r.y = fmaxf(r.y, v.y);
                r.z = fmaxf(r.z, v.z);
                r.w = fmaxf(r.w, v.w);
            }
        }
    }
    ((float4*)out)[(size_t)bm * (H_ / 4) + t] = r;
}

// ---------------------------------------------------------------------------
// Kernel 2: split-bf16 mma.sync GEMM + fused tanh/w_ctx epilogue
//   grid (6 n-blocks, 128 m-tiles), 256 threads (8 warps, warp tile 64x32)
//   BM=128 BN=128 BK=32, 3-stage cp.async pipeline (wait_group 1),
//   fragment reuse across split-terms, compile-time stage indices
// ---------------------------------------------------------------------------
#define SA_HI 0
#define SA_LO 8192
#define SB_HI 16384
#define SB_LO 24576
#define BUFSZ 32768
#define STAGES 3
#define SM_REQ (STAGES * BUFSZ)

__global__ __launch_bounds__(256, 2) void gemm_mma_kernel(
    const float* __restrict__ b_attn, const float* __restrict__ w_ctx) {

    extern __shared__ __align__(128) char smb[];
    uint32_t sbu = smem_u32(smb);

    int tid  = threadIdx.x;
    int wid  = tid >> 5, lane = tid & 31;
    int wm   = wid >> 2, wn = wid & 3;        // warp grid 2(m) x 4(n)
    int n0   = blockIdx.x * 128;

    const char* gA_hi = (const char*)Xfrag_hi + (size_t)blockIdx.y * 24 * 8192;
    const char* gA_lo = (const char*)Xfrag_lo + (size_t)blockIdx.y * 24 * 8192;
    const char* gB_hi = (const char*)Wfrag_hi + (size_t)blockIdx.x * 24 * 8192;
    const char* gB_lo = (const char*)Wfrag_lo + (size_t)blockIdx.x * 24 * 8192;

    float d[4][4][4];
#pragma unroll
    for (int i = 0; i < 4; i++)
#pragma unroll
        for (int j = 0; j < 4; j++)
#pragma unroll
            for (int r = 0; r < 4; r++) d[i][j][r] = 0.f;

    // linear 16B staging: 8KB per region, 2 cp.async16/thread/region
    auto stage = [&](int c, uint32_t buf) {
        size_t tb = (size_t)c * 8192;
#pragma unroll
        for (int p = 0; p < 2; p++) {
            uint32_t off = (uint32_t)(tid + p * 256) * 16;
            CP_ASYNC16(buf + SA_HI + off, gA_hi + tb + off);
            CP_ASYNC16(buf + SA_LO + off, gA_lo + tb + off);
            CP_ASYNC16(buf + SB_HI + off, gB_hi + tb + off);
            CP_ASYNC16(buf + SB_LO + off, gB_lo + tb + off);
        }
    };

    // compute with fragment reuse: per ks, load Ahi/Bhi/Blo once, run
    // terms (Ahi*Bhi) and (Ahi*Blo); then load Alo, run (Alo*Bhi).
    auto compute = [&](const char* buf) {
#pragma unroll
        for (int ks = 0; ks < 2; ks++) {
            uint32_t ah[4][4], al[4][4], bh[4][2], bl[4][2];
#pragma unroll
            for (int mt = 0; mt < 4; mt++) {
                uint32_t aoff = (((wm * 4 + mt) * 2 + ks) * 32 + lane) * 16;
                uint4 v = *(const uint4*)(buf + SA_HI + aoff);
                ah[mt][0] = v.x; ah[mt][1] = v.y; ah[mt][2] = v.z; ah[mt][3] = v.w;
            }
#pragma unroll
            for (int nt = 0; nt < 4; nt++) {
                uint32_t boff = (((wn * 4 + nt) * 2 + ks) * 32 + lane) * 8;
                uint2 vh = *(const uint2*)(buf + SB_HI + boff);
                bh[nt][0] = vh.x; bh[nt][1] = vh.y;
                uint2 vl = *(const uint2*)(buf + SB_LO + boff);
                bl[nt][0] = vl.x; bl[nt][1] = vl.y;
            }
#pragma unroll
            for (int mt = 0; mt < 4; mt++)
#pragma unroll
                for (int nt = 0; nt < 4; nt++)
                    mma_bf16(d[mt][nt], ah[mt], bh[nt]);
#pragma unroll
            for (int mt = 0; mt < 4; mt++)
#pragma unroll
                for (int nt = 0; nt < 4; nt++)
                    mma_bf16(d[mt][nt], ah[mt], bl[nt]);
#pragma unroll
            for (int mt = 0; mt < 4; mt++) {
                uint32_t aoff = (((wm * 4 + mt) * 2 + ks) * 32 + lane) * 16;
                uint4 v = *(const uint4*)(buf + SA_LO + aoff);
                al[mt][0] = v.x; al[mt][1] = v.y; al[mt][2] = v.z; al[mt][3] = v.w;
            }
#pragma unroll
            for (int mt = 0; mt < 4; mt++)
#pragma unroll
                for (int nt = 0; nt < 4; nt++)
                    mma_bf16(d[mt][nt], al[mt], bh[nt]);
        }
    };

    // ---- prologue: stages 0 and 1 in flight ----
    stage(0, sbu);
    CP_COMMIT();
    stage(1, sbu + BUFSZ);
    CP_COMMIT();

    // ---- mainloop: 24 chunks of K=32, 3-stage pipeline,
    //      cb step 3 so stage index (c % 3) folds to compile-time j ----
    for (int cb = 0; cb < 24; cb += 3) {
#pragma unroll
        for (int j = 0; j < 3; j++) {
            int c = cb + j;
            if (c == 23) CP_WAIT0(); else CP_WAIT1();   // oldest group (c) done
            __syncthreads();
            compute(smb + j * BUFSZ);
            if (c + 2 < 24) {
                stage(c + 2, sbu + ((j + 2) % 3) * BUFSZ);
                CP_COMMIT();
            }
        }
    }

    // ---- fused epilogue: partial logit = sum_n tanh(z + b) * w ----
    int q = lane & 3, g = lane >> 2;
    float bv[4][2], wv[4][2];
#pragma unroll
    for (int nt = 0; nt < 4; nt++)
#pragma unroll
        for (int c = 0; c < 2; c++) {
            int n = n0 + wn * 32 + nt * 8 + 2 * q + c;
            bv[nt][c] = b_attn[n];
            wv[nt][c] = w_ctx[n];
        }

    int slice = blockIdx.x * 4 + wn;
    int m0 = blockIdx.y * 128;
#pragma unroll
    for (int mt = 0; mt < 4; mt++) {
        float s0 = 0.f, s1 = 0.f;
#pragma unroll
        for (int nt = 0; nt < 4; nt++)
#pragma unroll
            for (int c = 0; c < 2; c++) {
                s0 += tanh_fast(d[mt][nt][c]     + bv[nt][c]) * wv[nt][c];
                s1 += tanh_fast(d[mt][nt][2 + c] + bv[nt][c]) * wv[nt][c];
            }
        s0 += __shfl_xor_sync(0xffffffffu, s0, 1);
        s0 += __shfl_xor_sync(0xffffffffu, s0, 2);
        s1 += __shfl_xor_sync(0xffffffffu, s1, 1);
        s1 += __shfl_xor_sync(0xffffffffu, s1, 2);
        if (q == 0) {
            int mg = m0 + wm * 64 + mt * 16 + g;
            g_part[slice * M_ + mg]     = s0;
            g_part[slice * M_ + mg + 8] = s1;
        }
    }
}

// ---------------------------------------------------------------------------
// Kernel 3a: softmax weights a[b,s] from 24 partial-logit slices
// ---------------------------------------------------------------------------
__global__ __launch_bounds__(256) void attn_weights_kernel() {
    int b = blockIdx.x, t = threadIdx.x;
    __shared__ float lg[S_];
    __shared__ float red[256];

    for (int s = t; s < S_; s += 256) {
        float v = 0.f;
#pragma unroll
        for (int nt = 0; nt < NT_; nt++) v += g_part[nt * M_ + b * S_ + s];
        lg[s] = v;
    }
    __syncthreads();

    float mx = fmaxf(lg[t], lg[t + 256]);
    red[t] = mx;
    __syncthreads();
    for (int o = 128; o > 0; o >>= 1) {
        if (t < o) red[t] = fmaxf(red[t], red[t + o]);
        __syncthreads();
    }
    mx = red[0];
    __syncthreads();

    float e0 = __expf(lg[t] - mx);
    float e1 = __expf(lg[t + 256] - mx);
    red[t] = e0 + e1;
    __syncthreads();
    for (int o = 128; o > 0; o >>= 1) {
        if (t < o) red[t] += red[t + o];
        __syncthreads();
    }
    float inv = 1.0f / red[0];

    g_attn[b * S_ + t]       = e0 * inv;
    g_attn[b * S_ + t + 256] = e1 * inv;
}

// ---------------------------------------------------------------------------
// Kernel 3b: partial weighted sums
// ---------------------------------------------------------------------------
__global__ __launch_bounds__(128) void wsum_partial_kernel(
    const float* __restrict__ X) {
    int b = blockIdx.x, hc = blockIdx.y, sc = blockIdx.z;
    int t = threadIdx.x;
    int h = hc * 128 + t;

    const float* Xp = X + (size_t)b * S_ * H_ + (size_t)sc * 64 * H_ + h;
    const float* ap = g_attn + b * S_ + sc * 64;

    float acc = 0.f;
#pragma unroll 8
    for (int s = 0; s < 64; s++)
        acc = fmaf(ap[s], Xp[(size_t)s * H_], acc);

    g_sacc[(((b * 6) + hc) * 8 + sc) * 128 + t] = acc;
}

// ---------------------------------------------------------------------------
// Kernel 3c: reduce 8 s-chunk partials -> sent_repr
// ---------------------------------------------------------------------------
__global__ __launch_bounds__(128) void wsum_reduce_kernel(float* __restrict__ sent) {
    int b = blockIdx.x, hc = blockIdx.y, t = threadIdx.x;
    const float* p = g_sacc + (((b * 6) + hc) * 8) * 128 + t;
    float acc = 0.f;
#pragma unroll
    for (int sc = 0; sc < 8; sc++) acc += p[sc * 128];
    sent[b * H_ + hc * 128 + t] = acc;
}

// ---------------------------------------------------------------------------
// launch
// ---------------------------------------------------------------------------
extern "C" void kernel_launch(void* const* d_in, const int* in_sizes, int n_in,
                              void* d_out, int out_size) {
    const float* X       = (const float*)d_in[0];
    const int* segments  = (const int*)d_in[1];
    const int* smask     = (const int*)d_in[2];
    const int* imask     = (const int*)d_in[3];
    const float* W       = (const float*)d_in[4];
    const float* b_attn  = (const float*)d_in[5];
    const float* w_ctx   = (const float*)d_in[6];

    float* out_vectors = (float*)d_out;
    float* sent        = (float*)d_out + (size_t)B_ * MS_ * H_;

    cudaFuncSetAttribute(gemm_mma_kernel,
                         cudaFuncAttributeMaxDynamicSharedMemorySize, SM_REQ);

    wsplit_fm_kernel<<<dim3(24, 6), 256>>>(W);
    xsplit_fm_kernel<<<dim3(24, 128), 256>>>(X);
    gather_max_kernel<<<B_ * MS_, 192>>>(X, segments, smask, imask, out_vectors);
    gemm_mma_kernel<<<dim3(6, 128), 256, SM_REQ>>>(b_attn, w_ctx);
    attn_weights_kernel<<<B_, 256>>>();
    wsum_partial_kernel<<<dim3(B_, 6, 8), 128>>>(X);
    wsum_reduce_kernel<<<dim3(B_, 6), 128>>>(sent);
}

// round 10
// speedup vs baseline: 3.4422x; 1.3141x over previous
#include <cuda_runtime.h>
#include <cuda_fp16.h>
#include <cstdint>

// Problem sizes (fixed by the dataset)
#define B_  32
#define S_  512
#define H_  768
#define MS_ 128
#define SL_ 8
#define M_  (B_ * S_)        // 16384 rows of X
#define NT_ 24               // partial-logit slices (6 n-blocks x 4 n-warps)

#define NEG_INF -1e30f

// Scratch (device globals: no allocation allowed)
__device__ float g_part[NT_ * M_];                 // partial logits per n-slice
__device__ float g_attn[M_];                       // softmax weights a[b,s]
__device__ float g_sacc[B_ * 6 * 8 * 128];         // weighted-sum partials
// Fragment-major tiles: per (tile, chunk) 2048 words (8KB).
// A: single fp16; B: fp16 hi/lo split (z = fp16(A) * (Bhi + Blo)).
__device__ uint4 Xfrag[M_ * H_ / 8];
__device__ uint4 Wfrag_hi[H_ * H_ / 8];
__device__ uint4 Wfrag_lo[H_ * H_ / 8];

// ---------------------------------------------------------------------------
// helpers
// ---------------------------------------------------------------------------
__device__ __forceinline__ uint32_t smem_u32(const void* p) {
    uint32_t a;
    asm("{ .reg .u64 t; cvta.to.shared.u64 t, %1; cvt.u32.u64 %0, t; }"
        : "=r"(a) : "l"(p));
    return a;
}

#define CP_ASYNC16(dst, src) \
    asm volatile("cp.async.cg.shared.global [%0], [%1], 16;" :: "r"(dst), "l"(src))
#define CP_COMMIT() asm volatile("cp.async.commit_group;" ::: "memory")
#define CP_WAIT0()  asm volatile("cp.async.wait_group 0;" ::: "memory")
#define CP_WAIT1()  asm volatile("cp.async.wait_group 1;" ::: "memory")

__device__ __forceinline__ void mma_f16(float* d, const uint32_t* a, const uint32_t* b) {
    asm volatile("mma.sync.aligned.m16n8k16.row.col.f32.f16.f16.f32 "
        "{%0,%1,%2,%3}, {%4,%5,%6,%7}, {%8,%9}, {%0,%1,%2,%3};"
        : "+f"(d[0]), "+f"(d[1]), "+f"(d[2]), "+f"(d[3])
        : "r"(a[0]), "r"(a[1]), "r"(a[2]), "r"(a[3]), "r"(b[0]), "r"(b[1]));
}

// fast tanh: tanh(x) = 1 - 2/(exp(2x)+1). 2 MUFU, abs err ~1e-6.
__device__ __forceinline__ float tanh_fast(float x) {
    float e = __expf(2.0f * x);
    return 1.0f - __fdividef(2.0f, e + 1.0f);
}

// pack two fp32 -> fp16x2 word
__device__ __forceinline__ uint32_t pack_h2(float x0, float x1) {
    __half h0 = __float2half_rn(x0);
    __half h1 = __float2half_rn(x1);
    return (uint32_t)__half_as_ushort(h0) | ((uint32_t)__half_as_ushort(h1) << 16);
}
// fp16 hi/lo split of two fp32 values
__device__ __forceinline__ void split2h(float x0, float x1, uint32_t& hw, uint32_t& lw) {
    __half h0 = __float2half_rn(x0);
    __half h1 = __float2half_rn(x1);
    __half l0 = __float2half_rn(x0 - __half2float(h0));
    __half l1 = __float2half_rn(x1 - __half2float(h1));
    hw = (uint32_t)__half_as_ushort(h0) | ((uint32_t)__half_as_ushort(h1) << 16);
    lw = (uint32_t)__half_as_ushort(l0) | ((uint32_t)__half_as_ushort(l1) << 16);
}

// ---------------------------------------------------------------------------
// Fragment word layouts (word index within an 8KB tile of 2048 words)
//   A tile: 128m x 32k.  W = ((mt*2+ks)*32 + lane)*4 + r
//   B tile: 128n x 32k.  W = ((nt*2+ks)*32 + lane)*2 + r
// ---------------------------------------------------------------------------

// Kernel 0a: X -> Xfrag (fp16), fragment-major tiles. grid (24 chunks, 128 mtiles)
__global__ __launch_bounds__(256) void xsplit_fm_kernel(const float* __restrict__ X) {
    __shared__ float sX[128][33];
    int c  = blockIdx.x;            // k-chunk 0..23
    int mb = blockIdx.y;            // m-tile 0..127
    int t  = threadIdx.x;

#pragma unroll
    for (int i = 0; i < 16; i++) {
        int idx = t + i * 256;      // 0..4095
        int m = idx >> 5, k = idx & 31;
        sX[m][k] = X[(size_t)(mb * 128 + m) * H_ + c * 32 + k];
    }
    __syncthreads();

    uint32_t* oh = (uint32_t*)Xfrag + ((size_t)mb * 24 + c) * 2048;
#pragma unroll
    for (int p = 0; p < 8; p++) {
        int w = t + p * 256;        // 0..2047
        int r = w & 3, lane = (w >> 2) & 31, g = w >> 7;   // g = mt*2+ks
        int mt = g >> 1, ks = g & 1;
        int m  = mt * 16 + ((r & 1) << 3) + (lane >> 2);
        int kp = ks * 8 + ((r >> 1) << 2) + (lane & 3);
        oh[w] = pack_h2(sX[m][2 * kp], sX[m][2 * kp + 1]);
    }
}

// Kernel 0b: W -> Wfrag_hi/lo (transposed: tiles over n). grid (24 chunks, 6 nblocks)
__global__ __launch_bounds__(256) void wsplit_fm_kernel(const float* __restrict__ W) {
    __shared__ float sW[32][129];
    int c  = blockIdx.x;            // k-chunk 0..23
    int nb = blockIdx.y;            // n-block 0..5
    int t  = threadIdx.x;

#pragma unroll
    for (int i = 0; i < 16; i++) {
        int idx = t + i * 256;      // 0..4095
        int k = idx >> 7, n = idx & 127;
        sW[k][n] = W[(size_t)(c * 32 + k) * H_ + nb * 128 + n];
    }
    __syncthreads();

    uint32_t* oh = (uint32_t*)Wfrag_hi + ((size_t)nb * 24 + c) * 2048;
    uint32_t* ol = (uint32_t*)Wfrag_lo + ((size_t)nb * 24 + c) * 2048;
#pragma unroll
    for (int p = 0; p < 8; p++) {
        int w = t + p * 256;
        int r = w & 1, lane = (w >> 1) & 31, g = w >> 6;   // g = nt*2+ks
        int nt = g >> 1, ks = g & 1;
        int n  = nt * 8 + (lane >> 2);
        int kp = ks * 8 + (r << 2) + (lane & 3);
        uint32_t hw, lw;
        split2h(sW[2 * kp][n], sW[2 * kp + 1][n], hw, lw);
        oh[w] = hw;
        ol[w] = lw;
    }
}

// ---------------------------------------------------------------------------
// Kernel 1: out_vectors = masked segment max (or pad row S-2)
// ---------------------------------------------------------------------------
__global__ void gather_max_kernel(const float* __restrict__ X,
                                  const int* __restrict__ segments,
                                  const int* __restrict__ seg_mask,
                                  const int* __restrict__ idx_mask,
                                  float* __restrict__ out) {
    int bm = blockIdx.x;
    int b  = bm >> 7;
    int t  = threadIdx.x;

    __shared__ int sidx[SL_];
    __shared__ int svalid[SL_];
    if (t < SL_) {
        sidx[t]   = segments[bm * SL_ + t];
        svalid[t] = idx_mask[bm * SL_ + t];
    }
    __syncthreads();

    const float4* Xb = (const float4*)(X + (size_t)b * S_ * H_);
    bool ok = seg_mask[bm] != 0;

    float4 r;
    if (!ok) {
        r = Xb[(size_t)(S_ - 2) * (H_ / 4) + t];
    } else {
        r = make_float4(NEG_INF, NEG_INF, NEG_INF, NEG_INF);
#pragma unroll
        for (int sl = 0; sl < SL_; sl++) {
            if (svalid[sl]) {
                float4 v = Xb[(size_t)sidx[sl] * (H_ / 4) + t];
                r.x = fmaxf(r.x, v.x);
                r.y = fmaxf(r.y, v.y);
                r.z = fmaxf(r.z, v.z);
                r.w = fmaxf(r.w, v.w);
            }
        }
    }
    ((float4*)out)[(size_t)bm * (H_ / 4) + t] = r;
}

// ---------------------------------------------------------------------------
// Kernel 2: fp16 2-term mma.sync GEMM + fused tanh/w_ctx epilogue
//   z = fp16(A) * (Bhi + Blo)
//   grid (6 n-blocks, 128 m-tiles), 256 threads (8 warps, warp tile 64x32)
//   BM=128 BN=128 BK=32, 3-stage cp.async pipeline (wait_group 1)
// ---------------------------------------------------------------------------
#define SA_HI 0
#define SB_HI 8192
#define SB_LO 16384
#define BUFSZ 24576
#define STAGES 3
#define SM_REQ (STAGES * BUFSZ)

__global__ __launch_bounds__(256, 2) void gemm_mma_kernel(
    const float* __restrict__ b_attn, const float* __restrict__ w_ctx) {

    extern __shared__ __align__(128) char smb[];
    uint32_t sbu = smem_u32(smb);

    int tid  = threadIdx.x;
    int wid  = tid >> 5, lane = tid & 31;
    int wm   = wid >> 2, wn = wid & 3;        // warp grid 2(m) x 4(n)
    int n0   = blockIdx.x * 128;

    const char* gA    = (const char*)Xfrag    + (size_t)blockIdx.y * 24 * 8192;
    const char* gB_hi = (const char*)Wfrag_hi + (size_t)blockIdx.x * 24 * 8192;
    const char* gB_lo = (const char*)Wfrag_lo + (size_t)blockIdx.x * 24 * 8192;

    float d[4][4][4];
#pragma unroll
    for (int i = 0; i < 4; i++)
#pragma unroll
        for (int j = 0; j < 4; j++)
#pragma unroll
            for (int r = 0; r < 4; r++) d[i][j][r] = 0.f;

    // linear 16B staging: 8KB per region, 2 cp.async16/thread/region
    auto stage = [&](int c, uint32_t buf) {
        size_t tb = (size_t)c * 8192;
#pragma unroll
        for (int p = 0; p < 2; p++) {
            uint32_t off = (uint32_t)(tid + p * 256) * 16;
            CP_ASYNC16(buf + SA_HI + off, gA    + tb + off);
            CP_ASYNC16(buf + SB_HI + off, gB_hi + tb + off);
            CP_ASYNC16(buf + SB_LO + off, gB_lo + tb + off);
        }
    };

    // compute: per ks load A, Bhi, Blo once; run A*Bhi then A*Blo.
    auto compute = [&](const char* buf) {
#pragma unroll
        for (int ks = 0; ks < 2; ks++) {
            uint32_t a[4][4], bh[4][2], bl[4][2];
#pragma unroll
            for (int mt = 0; mt < 4; mt++) {
                uint32_t aoff = (((wm * 4 + mt) * 2 + ks) * 32 + lane) * 16;
                uint4 v = *(const uint4*)(buf + SA_HI + aoff);
                a[mt][0] = v.x; a[mt][1] = v.y; a[mt][2] = v.z; a[mt][3] = v.w;
            }
#pragma unroll
            for (int nt = 0; nt < 4; nt++) {
                uint32_t boff = (((wn * 4 + nt) * 2 + ks) * 32 + lane) * 8;
                uint2 vh = *(const uint2*)(buf + SB_HI + boff);
                bh[nt][0] = vh.x; bh[nt][1] = vh.y;
                uint2 vl = *(const uint2*)(buf + SB_LO + boff);
                bl[nt][0] = vl.x; bl[nt][1] = vl.y;
            }
#pragma unroll
            for (int mt = 0; mt < 4; mt++)
#pragma unroll
                for (int nt = 0; nt < 4; nt++)
                    mma_f16(d[mt][nt], a[mt], bh[nt]);
#pragma unroll
            for (int mt = 0; mt < 4; mt++)
#pragma unroll
                for (int nt = 0; nt < 4; nt++)
                    mma_f16(d[mt][nt], a[mt], bl[nt]);
        }
    };

    // ---- prologue: stages 0 and 1 in flight ----
    stage(0, sbu);
    CP_COMMIT();
    stage(1, sbu + BUFSZ);
    CP_COMMIT();

    // ---- mainloop: 24 chunks of K=32, 3-stage pipeline,
    //      cb step 3 so stage index (c % 3) folds to compile-time j ----
    for (int cb = 0; cb < 24; cb += 3) {
#pragma unroll
        for (int j = 0; j < 3; j++) {
            int c = cb + j;
            if (c == 23) CP_WAIT0(); else CP_WAIT1();   // oldest group (c) done
            __syncthreads();
            compute(smb + j * BUFSZ);
            if (c + 2 < 24) {
                stage(c + 2, sbu + ((j + 2) % 3) * BUFSZ);
                CP_COMMIT();
            }
        }
    }

    // ---- fused epilogue: partial logit = sum_n tanh(z + b) * w ----
    int q = lane & 3, g = lane >> 2;
    float bv[4][2], wv[4][2];
#pragma unroll
    for (int nt = 0; nt < 4; nt++)
#pragma unroll
        for (int c = 0; c < 2; c++) {
            int n = n0 + wn * 32 + nt * 8 + 2 * q + c;
            bv[nt][c] = b_attn[n];
            wv[nt][c] = w_ctx[n];
        }

    int slice = blockIdx.x * 4 + wn;
    int m0 = blockIdx.y * 128;
#pragma unroll
    for (int mt = 0; mt < 4; mt++) {
        float s0 = 0.f, s1 = 0.f;
#pragma unroll
        for (int nt = 0; nt < 4; nt++)
#pragma unroll
            for (int c = 0; c < 2; c++) {
                s0 += tanh_fast(d[mt][nt][c]     + bv[nt][c]) * wv[nt][c];
                s1 += tanh_fast(d[mt][nt][2 + c] + bv[nt][c]) * wv[nt][c];
            }
        s0 += __shfl_xor_sync(0xffffffffu, s0, 1);
        s0 += __shfl_xor_sync(0xffffffffu, s0, 2);
        s1 += __shfl_xor_sync(0xffffffffu, s1, 1);
        s1 += __shfl_xor_sync(0xffffffffu, s1, 2);
        if (q == 0) {
            int mg = m0 + wm * 64 + mt * 16 + g;
            g_part[slice * M_ + mg]     = s0;
            g_part[slice * M_ + mg + 8] = s1;
        }
    }
}

// ---------------------------------------------------------------------------
// Kernel 3a: softmax weights a[b,s] from 24 partial-logit slices
// ---------------------------------------------------------------------------
__global__ __launch_bounds__(256) void attn_weights_kernel() {
    int b = blockIdx.x, t = threadIdx.x;
    __shared__ float lg[S_];
    __shared__ float red[256];

    for (int s = t; s < S_; s += 256) {
        float v = 0.f;
#pragma unroll
        for (int nt = 0; nt < NT_; nt++) v += g_part[nt * M_ + b * S_ + s];
        lg[s] = v;
    }
    __syncthreads();

    float mx = fmaxf(lg[t], lg[t + 256]);
    red[t] = mx;
    __syncthreads();
    for (int o = 128; o > 0; o >>= 1) {
        if (t < o) red[t] = fmaxf(red[t], red[t + o]);
        __syncthreads();
    }
    mx = red[0];
    __syncthreads();

    float e0 = __expf(lg[t] - mx);
    float e1 = __expf(lg[t + 256] - mx);
    red[t] = e0 + e1;
    __syncthreads();
    for (int o = 128; o > 0; o >>= 1) {
        if (t < o) red[t] += red[t + o];
        __syncthreads();
    }
    float inv = 1.0f / red[0];

    g_attn[b * S_ + t]       = e0 * inv;
    g_attn[b * S_ + t + 256] = e1 * inv;
}

// ---------------------------------------------------------------------------
// Kernel 3b: partial weighted sums
// ---------------------------------------------------------------------------
__global__ __launch_bounds__(128) void wsum_partial_kernel(
    const float* __restrict__ X) {
    int b = blockIdx.x, hc = blockIdx.y, sc = blockIdx.z;
    int t = threadIdx.x;
    int h = hc * 128 + t;

    const float* Xp = X + (size_t)b * S_ * H_ + (size_t)sc * 64 * H_ + h;
    const float* ap = g_attn + b * S_ + sc * 64;

    float acc = 0.f;
#pragma unroll 8
    for (int s = 0; s < 64; s++)
        acc = fmaf(ap[s], Xp[(size_t)s * H_], acc);

    g_sacc[(((b * 6) + hc) * 8 + sc) * 128 + t] = acc;
}

// ---------------------------------------------------------------------------
// Kernel 3c: reduce 8 s-chunk partials -> sent_repr
// ---------------------------------------------------------------------------
__global__ __launch_bounds__(128) void wsum_reduce_kernel(float* __restrict__ sent) {
    int b = blockIdx.x, hc = blockIdx.y, t = threadIdx.x;
    const float* p = g_sacc + (((b * 6) + hc) * 8) * 128 + t;
    float acc = 0.f;
#pragma unroll
    for (int sc = 0; sc < 8; sc++) acc += p[sc * 128];
    sent[b * H_ + hc * 128 + t] = acc;
}

// ---------------------------------------------------------------------------
// launch
// ---------------------------------------------------------------------------
extern "C" void kernel_launch(void* const* d_in, const int* in_sizes, int n_in,
                              void* d_out, int out_size) {
    const float* X       = (const float*)d_in[0];
    const int* segments  = (const int*)d_in[1];
    const int* smask     = (const int*)d_in[2];
    const int* imask     = (const int*)d_in[3];
    const float* W       = (const float*)d_in[4];
    const float* b_attn  = (const float*)d_in[5];
    const float* w_ctx   = (const float*)d_in[6];

    float* out_vectors = (float*)d_out;
    float* sent        = (float*)d_out + (size_t)B_ * MS_ * H_;

    cudaFuncSetAttribute(gemm_mma_kernel,
                         cudaFuncAttributeMaxDynamicSharedMemorySize, SM_REQ);

    wsplit_fm_kernel<<<dim3(24, 6), 256>>>(W);
    xsplit_fm_kernel<<<dim3(24, 128), 256>>>(X);
    gather_max_kernel<<<B_ * MS_, 192>>>(X, segments, smask, imask, out_vectors);
    gemm_mma_kernel<<<dim3(6, 128), 256, SM_REQ>>>(b_attn, w_ctx);
    attn_weights_kernel<<<B_, 256>>>();
    wsum_partial_kernel<<<dim3(B_, 6, 8), 128>>>(X);
    wsum_reduce_kernel<<<dim3(B_, 6), 128>>>(sent);
}

// round 11
// speedup vs baseline: 4.9404x; 1.4352x over previous
#include <cuda_runtime.h>
#include <cuda_fp16.h>
#include <cstdint>

// Problem sizes (fixed by the dataset)
#define B_  32
#define S_  512
#define H_  768
#define MS_ 128
#define SL_ 8
#define M_  (B_ * S_)        // 16384 rows of X
#define NT_ 24               // partial-logit slices (6 n-blocks x 4 n-warps)

#define NEG_INF -1e30f

// Scratch (device globals: no allocation allowed)
__device__ float g_part[NT_ * M_];                 // partial logits per n-slice
__device__ float g_attn[M_];                       // softmax weights a[b,s]
__device__ float g_sacc[B_ * 6 * 8 * 128];         // weighted-sum partials
// Fragment-major tiles: per (tile, chunk32) 2048 words (8KB), fp16.
__device__ uint4 Xfrag[M_ * H_ / 8];
__device__ uint4 Wfrag[H_ * H_ / 8];

// ---------------------------------------------------------------------------
// helpers
// ---------------------------------------------------------------------------
__device__ __forceinline__ uint32_t smem_u32(const void* p) {
    uint32_t a;
    asm("{ .reg .u64 t; cvta.to.shared.u64 t, %1; cvt.u32.u64 %0, t; }"
        : "=r"(a) : "l"(p));
    return a;
}

#define CP_ASYNC16(dst, src) \
    asm volatile("cp.async.cg.shared.global [%0], [%1], 16;" :: "r"(dst), "l"(src))
#define CP_COMMIT() asm volatile("cp.async.commit_group;" ::: "memory")
#define CP_WAIT0()  asm volatile("cp.async.wait_group 0;" ::: "memory")
#define CP_WAIT1()  asm volatile("cp.async.wait_group 1;" ::: "memory")

__device__ __forceinline__ void mma_f16(float* d, const uint32_t* a, const uint32_t* b) {
    asm volatile("mma.sync.aligned.m16n8k16.row.col.f32.f16.f16.f32 "
        "{%0,%1,%2,%3}, {%4,%5,%6,%7}, {%8,%9}, {%0,%1,%2,%3};"
        : "+f"(d[0]), "+f"(d[1]), "+f"(d[2]), "+f"(d[3])
        : "r"(a[0]), "r"(a[1]), "r"(a[2]), "r"(a[3]), "r"(b[0]), "r"(b[1]));
}

// fast tanh: tanh(x) = 1 - 2/(exp(2x)+1). 2 MUFU, abs err ~1e-6.
__device__ __forceinline__ float tanh_fast(float x) {
    float e = __expf(2.0f * x);
    return 1.0f - __fdividef(2.0f, e + 1.0f);
}

// pack two fp32 -> fp16x2 word
__device__ __forceinline__ uint32_t pack_h2(float x0, float x1) {
    __half h0 = __float2half_rn(x0);
    __half h1 = __float2half_rn(x1);
    return (uint32_t)__half_as_ushort(h0) | ((uint32_t)__half_as_ushort(h1) << 16);
}

// ---------------------------------------------------------------------------
// Fragment word layouts (word index within an 8KB chunk32 tile of 2048 words)
//   A tile: 128m x 32k.  W = ((mt*2+ks)*32 + lane)*4 + r
//   B tile: 128n x 32k.  W = ((nt*2+ks)*32 + lane)*2 + r
// ---------------------------------------------------------------------------

// Kernel 0a: X -> Xfrag (fp16), fragment-major tiles. grid (24 chunks, 128 mtiles)
__global__ __launch_bounds__(256) void xsplit_fm_kernel(const float* __restrict__ X) {
    __shared__ float sX[128][33];
    int c  = blockIdx.x;            // k-chunk32 0..23
    int mb = blockIdx.y;            // m-tile 0..127
    int t  = threadIdx.x;

#pragma unroll
    for (int i = 0; i < 16; i++) {
        int idx = t + i * 256;      // 0..4095
        int m = idx >> 5, k = idx & 31;
        sX[m][k] = X[(size_t)(mb * 128 + m) * H_ + c * 32 + k];
    }
    __syncthreads();

    uint32_t* oh = (uint32_t*)Xfrag + ((size_t)mb * 24 + c) * 2048;
#pragma unroll
    for (int p = 0; p < 8; p++) {
        int w = t + p * 256;        // 0..2047
        int r = w & 3, lane = (w >> 2) & 31, g = w >> 7;   // g = mt*2+ks
        int mt = g >> 1, ks = g & 1;
        int m  = mt * 16 + ((r & 1) << 3) + (lane >> 2);
        int kp = ks * 8 + ((r >> 1) << 2) + (lane & 3);
        oh[w] = pack_h2(sX[m][2 * kp], sX[m][2 * kp + 1]);
    }
}

// Kernel 0b: W -> Wfrag (fp16, transposed: tiles over n). grid (24 chunks, 6 nblocks)
__global__ __launch_bounds__(256) void wsplit_fm_kernel(const float* __restrict__ W) {
    __shared__ float sW[32][129];
    int c  = blockIdx.x;            // k-chunk32 0..23
    int nb = blockIdx.y;            // n-block 0..5
    int t  = threadIdx.x;

#pragma unroll
    for (int i = 0; i < 16; i++) {
        int idx = t + i * 256;      // 0..4095
        int k = idx >> 7, n = idx & 127;
        sW[k][n] = W[(size_t)(c * 32 + k) * H_ + nb * 128 + n];
    }
    __syncthreads();

    uint32_t* oh = (uint32_t*)Wfrag + ((size_t)nb * 24 + c) * 2048;
#pragma unroll
    for (int p = 0; p < 8; p++) {
        int w = t + p * 256;
        int r = w & 1, lane = (w >> 1) & 31, g = w >> 6;   // g = nt*2+ks
        int nt = g >> 1, ks = g & 1;
        int n  = nt * 8 + (lane >> 2);
        int kp = ks * 8 + (r << 2) + (lane & 3);
        oh[w] = pack_h2(sW[2 * kp][n], sW[2 * kp + 1][n]);
    }
}

// ---------------------------------------------------------------------------
// Kernel 1: out_vectors = masked segment max (or pad row S-2)
// ---------------------------------------------------------------------------
__global__ void gather_max_kernel(const float* __restrict__ X,
                                  const int* __restrict__ segments,
                                  const int* __restrict__ seg_mask,
                                  const int* __restrict__ idx_mask,
                                  float* __restrict__ out) {
    int bm = blockIdx.x;
    int b  = bm >> 7;
    int t  = threadIdx.x;

    __shared__ int sidx[SL_];
    __shared__ int svalid[SL_];
    if (t < SL_) {
        sidx[t]   = segments[bm * SL_ + t];
        svalid[t] = idx_mask[bm * SL_ + t];
    }
    __syncthreads();

    const float4* Xb = (const float4*)(X + (size_t)b * S_ * H_);
    bool ok = seg_mask[bm] != 0;

    float4 r;
    if (!ok) {
        r = Xb[(size_t)(S_ - 2) * (H_ / 4) + t];
    } else {
        r = make_float4(NEG_INF, NEG_INF, NEG_INF, NEG_INF);
#pragma unroll
        for (int sl = 0; sl < SL_; sl++) {
            if (svalid[sl]) {
                float4 v = Xb[(size_t)sidx[sl] * (H_ / 4) + t];
                r.x = fmaxf(r.x, v.x);
                r.y = fmaxf(r.y, v.y);
                r.z = fmaxf(r.z, v.z);
                r.w = fmaxf(r.w, v.w);
            }
        }
    }
    ((float4*)out)[(size_t)bm * (H_ / 4) + t] = r;
}

// ---------------------------------------------------------------------------
// Kernel 2: plain fp16 mma.sync GEMM + fused tanh/w_ctx epilogue
//   z = fp16(A) * fp16(W), fp32 accumulate
//   grid (6 n-blocks, 128 m-tiles), 256 threads (8 warps, warp tile 64x32)
//   BM=128 BN=128 BK=64 (two chunk32 images per stage), 12 iterations,
//   3-stage cp.async pipeline (wait_group 1)
// ---------------------------------------------------------------------------
#define SA_OFF 0
#define SB_OFF 16384
#define BUFSZ 32768
#define STAGES 3
#define SM_REQ (STAGES * BUFSZ)

__global__ __launch_bounds__(256, 2) void gemm_mma_kernel(
    const float* __restrict__ b_attn, const float* __restrict__ w_ctx) {

    extern __shared__ __align__(128) char smb[];
    uint32_t sbu = smem_u32(smb);

    int tid  = threadIdx.x;
    int wid  = tid >> 5, lane = tid & 31;
    int wm   = wid >> 2, wn = wid & 3;        // warp grid 2(m) x 4(n)
    int n0   = blockIdx.x * 128;

    const char* gA = (const char*)Xfrag + (size_t)blockIdx.y * 24 * 8192;
    const char* gB = (const char*)Wfrag + (size_t)blockIdx.x * 24 * 8192;

    float d[4][4][4];
#pragma unroll
    for (int i = 0; i < 4; i++)
#pragma unroll
        for (int j = 0; j < 4; j++)
#pragma unroll
            for (int r = 0; r < 4; r++) d[i][j][r] = 0.f;

    // staging: one chunk64 = two contiguous 8KB chunk32 images per operand
    auto stage = [&](int c, uint32_t buf) {   // c in chunk64 units (0..11)
        size_t tb = (size_t)c * 16384;
#pragma unroll
        for (int p = 0; p < 4; p++) {
            uint32_t off = (uint32_t)(tid + p * 256) * 16;
            CP_ASYNC16(buf + SA_OFF + off, gA + tb + off);
            CP_ASYNC16(buf + SB_OFF + off, gB + tb + off);
        }
    };

    auto compute = [&](const char* buf) {
#pragma unroll
        for (int half = 0; half < 2; half++) {
            const char* Ab = buf + SA_OFF + half * 8192;
            const char* Bb = buf + SB_OFF + half * 8192;
#pragma unroll
            for (int ks = 0; ks < 2; ks++) {
                uint32_t a[4][4], b[4][2];
#pragma unroll
                for (int mt = 0; mt < 4; mt++) {
                    uint32_t aoff = (((wm * 4 + mt) * 2 + ks) * 32 + lane) * 16;
                    uint4 v = *(const uint4*)(Ab + aoff);
                    a[mt][0] = v.x; a[mt][1] = v.y; a[mt][2] = v.z; a[mt][3] = v.w;
                }
#pragma unroll
                for (int nt = 0; nt < 4; nt++) {
                    uint32_t boff = (((wn * 4 + nt) * 2 + ks) * 32 + lane) * 8;
                    uint2 vb = *(const uint2*)(Bb + boff);
                    b[nt][0] = vb.x; b[nt][1] = vb.y;
                }
#pragma unroll
                for (int mt = 0; mt < 4; mt++)
#pragma unroll
                    for (int nt = 0; nt < 4; nt++)
                        mma_f16(d[mt][nt], a[mt], b[nt]);
            }
        }
    };

    // ---- prologue: stages 0 and 1 in flight ----
    stage(0, sbu);
    CP_COMMIT();
    stage(1, sbu + BUFSZ);
    CP_COMMIT();

    // ---- mainloop: 12 chunk64s, 3-stage pipeline, compile-time stage idx ----
    for (int cb = 0; cb < 12; cb += 3) {
#pragma unroll
        for (int j = 0; j < 3; j++) {
            int c = cb + j;
            if (c == 11) CP_WAIT0(); else CP_WAIT1();   // oldest group (c) done
            __syncthreads();
            compute(smb + j * BUFSZ);
            if (c + 2 < 12) {
                stage(c + 2, sbu + ((j + 2) % 3) * BUFSZ);
                CP_COMMIT();
            }
        }
    }

    // ---- fused epilogue: partial logit = sum_n tanh(z + b) * w ----
    int q = lane & 3, g = lane >> 2;
    float bv[4][2], wv[4][2];
#pragma unroll
    for (int nt = 0; nt < 4; nt++)
#pragma unroll
        for (int c = 0; c < 2; c++) {
            int n = n0 + wn * 32 + nt * 8 + 2 * q + c;
            bv[nt][c] = b_attn[n];
            wv[nt][c] = w_ctx[n];
        }

    int slice = blockIdx.x * 4 + wn;
    int m0 = blockIdx.y * 128;
#pragma unroll
    for (int mt = 0; mt < 4; mt++) {
        float s0 = 0.f, s1 = 0.f;
#pragma unroll
        for (int nt = 0; nt < 4; nt++)
#pragma unroll
            for (int c = 0; c < 2; c++) {
                s0 += tanh_fast(d[mt][nt][c]     + bv[nt][c]) * wv[nt][c];
                s1 += tanh_fast(d[mt][nt][2 + c] + bv[nt][c]) * wv[nt][c];
            }
        s0 += __shfl_xor_sync(0xffffffffu, s0, 1);
        s0 += __shfl_xor_sync(0xffffffffu, s0, 2);
        s1 += __shfl_xor_sync(0xffffffffu, s1, 1);
        s1 += __shfl_xor_sync(0xffffffffu, s1, 2);
        if (q == 0) {
            int mg = m0 + wm * 64 + mt * 16 + g;
            g_part[slice * M_ + mg]     = s0;
            g_part[slice * M_ + mg + 8] = s1;
        }
    }
}

// ---------------------------------------------------------------------------
// Kernel 3a: softmax weights a[b,s] from 24 partial-logit slices
// ---------------------------------------------------------------------------
__global__ __launch_bounds__(256) void attn_weights_kernel() {
    int b = blockIdx.x, t = threadIdx.x;
    __shared__ float lg[S_];
    __shared__ float red[256];

    for (int s = t; s < S_; s += 256) {
        float v = 0.f;
#pragma unroll
        for (int nt = 0; nt < NT_; nt++) v += g_part[nt * M_ + b * S_ + s];
        lg[s] = v;
    }
    __syncthreads();

    float mx = fmaxf(lg[t], lg[t + 256]);
    red[t] = mx;
    __syncthreads();
    for (int o = 128; o > 0; o >>= 1) {
        if (t < o) red[t] = fmaxf(red[t], red[t + o]);
        __syncthreads();
    }
    mx = red[0];
    __syncthreads();

    float e0 = __expf(lg[t] - mx);
    float e1 = __expf(lg[t + 256] - mx);
    red[t] = e0 + e1;
    __syncthreads();
    for (int o = 128; o > 0; o >>= 1) {
        if (t < o) red[t] += red[t + o];
        __syncthreads();
    }
    float inv = 1.0f / red[0];

    g_attn[b * S_ + t]       = e0 * inv;
    g_attn[b * S_ + t + 256] = e1 * inv;
}

// ---------------------------------------------------------------------------
// Kernel 3b: partial weighted sums
// ---------------------------------------------------------------------------
__global__ __launch_bounds__(128) void wsum_partial_kernel(
    const float* __restrict__ X) {
    int b = blockIdx.x, hc = blockIdx.y, sc = blockIdx.z;
    int t = threadIdx.x;
    int h = hc * 128 + t;

    const float* Xp = X + (size_t)b * S_ * H_ + (size_t)sc * 64 * H_ + h;
    const float* ap = g_attn + b * S_ + sc * 64;

    float acc = 0.f;
#pragma unroll 8
    for (int s = 0; s < 64; s++)
        acc = fmaf(ap[s], Xp[(size_t)s * H_], acc);

    g_sacc[(((b * 6) + hc) * 8 + sc) * 128 + t] = acc;
}

// ---------------------------------------------------------------------------
// Kernel 3c: reduce 8 s-chunk partials -> sent_repr
// ---------------------------------------------------------------------------
__global__ __launch_bounds__(128) void wsum_reduce_kernel(float* __restrict__ sent) {
    int b = blockIdx.x, hc = blockIdx.y, t = threadIdx.x;
    const float* p = g_sacc + (((b * 6) + hc) * 8) * 128 + t;
    float acc = 0.f;
#pragma unroll
    for (int sc = 0; sc < 8; sc++) acc += p[sc * 128];
    sent[b * H_ + hc * 128 + t] = acc;
}

// ---------------------------------------------------------------------------
// launch
// ---------------------------------------------------------------------------
extern "C" void kernel_launch(void* const* d_in, const int* in_sizes, int n_in,
                              void* d_out, int out_size) {
    const float* X       = (const float*)d_in[0];
    const int* segments  = (const int*)d_in[1];
    const int* smask     = (const int*)d_in[2];
    const int* imask     = (const int*)d_in[3];
    const float* W       = (const float*)d_in[4];
    const float* b_attn  = (const float*)d_in[5];
    const float* w_ctx   = (const float*)d_in[6];

    float* out_vectors = (float*)d_out;
    float* sent        = (float*)d_out + (size_t)B_ * MS_ * H_;

    cudaFuncSetAttribute(gemm_mma_kernel,
                         cudaFuncAttributeMaxDynamicSharedMemorySize, SM_REQ);

    wsplit_fm_kernel<<<dim3(24, 6), 256>>>(W);
    xsplit_fm_kernel<<<dim3(24, 128), 256>>>(X);
    gather_max_kernel<<<B_ * MS_, 192>>>(X, segments, smask, imask, out_vectors);
    gemm_mma_kernel<<<dim3(6, 128), 256, SM_REQ>>>(b_attn, w_ctx);
    attn_weights_kernel<<<B_, 256>>>();
    wsum_partial_kernel<<<dim3(B_, 6, 8), 128>>>(X);
    wsum_reduce_kernel<<<dim3(B_, 6), 128>>>(sent);
}

// round 12
// speedup vs baseline: 5.1419x; 1.0408x over previous
#include <cuda_runtime.h>
#include <cuda_fp16.h>
#include <cstdint>

// Problem sizes (fixed by the dataset)
#define B_  32
#define S_  512
#define H_  768
#define MS_ 128
#define SL_ 8
#define M_  (B_ * S_)        // 16384 rows of X
#define NT_ 24               // partial-logit slices (6 n-blocks x 4 n-warps)

#define NEG_INF -1e30f

// Scratch (device globals: no allocation allowed)
__device__ float g_part[NT_ * M_];                 // partial logits per n-slice
__device__ float g_attn[M_];                       // softmax weights a[b,s]
__device__ float g_sacc[B_ * 6 * 8 * 128];         // weighted-sum partials
// Fragment-major tiles: per (tile, chunk32) 2048 words (8KB), fp16.
__device__ uint4 Xfrag[M_ * H_ / 8];
__device__ uint4 Wfrag[H_ * H_ / 8];

// ---------------------------------------------------------------------------
// helpers
// ---------------------------------------------------------------------------
__device__ __forceinline__ uint32_t smem_u32(const void* p) {
    uint32_t a;
    asm("{ .reg .u64 t; cvta.to.shared.u64 t, %1; cvt.u32.u64 %0, t; }"
        : "=r"(a) : "l"(p));
    return a;
}

#define CP_ASYNC16(dst, src) \
    asm volatile("cp.async.cg.shared.global [%0], [%1], 16;" :: "r"(dst), "l"(src))
#define CP_COMMIT() asm volatile("cp.async.commit_group;" ::: "memory")
#define CP_WAIT0()  asm volatile("cp.async.wait_group 0;" ::: "memory")
#define CP_WAIT1()  asm volatile("cp.async.wait_group 1;" ::: "memory")

__device__ __forceinline__ void mma_f16(float* d, const uint32_t* a, const uint32_t* b) {
    asm volatile("mma.sync.aligned.m16n8k16.row.col.f32.f16.f16.f32 "
        "{%0,%1,%2,%3}, {%4,%5,%6,%7}, {%8,%9}, {%0,%1,%2,%3};"
        : "+f"(d[0]), "+f"(d[1]), "+f"(d[2]), "+f"(d[3])
        : "r"(a[0]), "r"(a[1]), "r"(a[2]), "r"(a[3]), "r"(b[0]), "r"(b[1]));
}

// fast tanh: tanh(x) = 1 - 2/(exp(2x)+1). 2 MUFU, abs err ~1e-6.
__device__ __forceinline__ float tanh_fast(float x) {
    float e = __expf(2.0f * x);
    return 1.0f - __fdividef(2.0f, e + 1.0f);
}

// pack two fp32 -> fp16x2 word
__device__ __forceinline__ uint32_t pack_h2(float x0, float x1) {
    __half h0 = __float2half_rn(x0);
    __half h1 = __float2half_rn(x1);
    return (uint32_t)__half_as_ushort(h0) | ((uint32_t)__half_as_ushort(h1) << 16);
}

// ---------------------------------------------------------------------------
// Fragment word layouts (word index within an 8KB chunk32 tile of 2048 words)
//   A tile: 128m x 32k.  W = ((mt*2+ks)*32 + lane)*4 + r
//     mt=m>>4, ks=kp>>3 (kp=k/2), lane=(m&7)*4+(kp&3), r=((m>>3)&1)+2*((kp>>2)&1)
//   B tile: 128n x 32k, PAIRED: for nt pair ntp=nt>>1, sub=nt&1:
//     W = ((ntp*2+ks)*32 + lane)*4 + sub*2 + r
//     one LDS.128 yields both registers of two adjacent n-tiles.
// ---------------------------------------------------------------------------

// Kernel 0: combined prepass. grid (24 chunks, 128+6):
//   y < 128 : X -> Xfrag (fp16 fragment-major)
//   y >= 128: W -> Wfrag (fp16, transposed, paired-B layout)
__global__ __launch_bounds__(256) void split_fm_kernel(
    const float* __restrict__ X, const float* __restrict__ W) {
    __shared__ float sbuf[4224];
    int c = blockIdx.x;             // k-chunk32 0..23
    int t = threadIdx.x;

    if (blockIdx.y < 128) {
        int mb = blockIdx.y;
        float (*sX)[33] = (float (*)[33])sbuf;   // [128][33]
#pragma unroll
        for (int i = 0; i < 16; i++) {
            int idx = t + i * 256;  // 0..4095
            int m = idx >> 5, k = idx & 31;
            sX[m][k] = X[(size_t)(mb * 128 + m) * H_ + c * 32 + k];
        }
        __syncthreads();

        uint32_t* oh = (uint32_t*)Xfrag + ((size_t)mb * 24 + c) * 2048;
#pragma unroll
        for (int p = 0; p < 8; p++) {
            int w = t + p * 256;    // 0..2047
            int r = w & 3, lane = (w >> 2) & 31, g = w >> 7;   // g = mt*2+ks
            int mt = g >> 1, ks = g & 1;
            int m  = mt * 16 + ((r & 1) << 3) + (lane >> 2);
            int kp = ks * 8 + ((r >> 1) << 2) + (lane & 3);
            oh[w] = pack_h2(sX[m][2 * kp], sX[m][2 * kp + 1]);
        }
    } else {
        int nb = blockIdx.y - 128;
        float (*sW)[129] = (float (*)[129])sbuf; // [32][129]
#pragma unroll
        for (int i = 0; i < 16; i++) {
            int idx = t + i * 256;  // 0..4095
            int k = idx >> 7, n = idx & 127;
            sW[k][n] = W[(size_t)(c * 32 + k) * H_ + nb * 128 + n];
        }
        __syncthreads();

        uint32_t* oh = (uint32_t*)Wfrag + ((size_t)nb * 24 + c) * 2048;
#pragma unroll
        for (int p = 0; p < 8; p++) {
            int w = t + p * 256;
            int r2 = w & 3, lane = (w >> 2) & 31, g = w >> 7;  // g = ntp*2+ks
            int sub = r2 >> 1, r = r2 & 1;
            int ntp = g >> 1, ks = g & 1;
            int nt = ntp * 2 + sub;
            int n  = nt * 8 + (lane >> 2);
            int kp = ks * 8 + (r << 2) + (lane & 3);
            oh[w] = pack_h2(sW[2 * kp][n], sW[2 * kp + 1][n]);
        }
    }
}

// ---------------------------------------------------------------------------
// Kernel 1: out_vectors = masked segment max (or pad row S-2)
// ---------------------------------------------------------------------------
__global__ void gather_max_kernel(const float* __restrict__ X,
                                  const int* __restrict__ segments,
                                  const int* __restrict__ seg_mask,
                                  const int* __restrict__ idx_mask,
                                  float* __restrict__ out) {
    int bm = blockIdx.x;
    int b  = bm >> 7;
    int t  = threadIdx.x;

    __shared__ int sidx[SL_];
    __shared__ int svalid[SL_];
    if (t < SL_) {
        sidx[t]   = segments[bm * SL_ + t];
        svalid[t] = idx_mask[bm * SL_ + t];
    }
    __syncthreads();

    const float4* Xb = (const float4*)(X + (size_t)b * S_ * H_);
    bool ok = seg_mask[bm] != 0;

    float4 r;
    if (!ok) {
        r = Xb[(size_t)(S_ - 2) * (H_ / 4) + t];
    } else {
        r = make_float4(NEG_INF, NEG_INF, NEG_INF, NEG_INF);
#pragma unroll
        for (int sl = 0; sl < SL_; sl++) {
            if (svalid[sl]) {
                float4 v = Xb[(size_t)sidx[sl] * (H_ / 4) + t];
                r.x = fmaxf(r.x, v.x);
                r.y = fmaxf(r.y, v.y);
                r.z = fmaxf(r.z, v.z);
                r.w = fmaxf(r.w, v.w);
            }
        }
    }
    ((float4*)out)[(size_t)bm * (H_ / 4) + t] = r;
}

// ---------------------------------------------------------------------------
// Kernel 2: plain fp16 mma.sync GEMM + fused tanh/w_ctx epilogue
//   z = fp16(A) * fp16(W), fp32 accumulate, paired-B LDS.128 feeds
//   grid (6 n-blocks, 128 m-tiles), 256 threads (8 warps, warp tile 64x32)
//   BM=128 BN=128 BK=64 (two chunk32 images per stage), 12 iterations,
//   3-stage cp.async pipeline (wait_group 1)
// ---------------------------------------------------------------------------
#define SA_OFF 0
#define SB_OFF 16384
#define BUFSZ 32768
#define STAGES 3
#define SM_REQ (STAGES * BUFSZ)

__global__ __launch_bounds__(256, 2) void gemm_mma_kernel(
    const float* __restrict__ b_attn, const float* __restrict__ w_ctx) {

    extern __shared__ __align__(128) char smb[];
    uint32_t sbu = smem_u32(smb);

    int tid  = threadIdx.x;
    int wid  = tid >> 5, lane = tid & 31;
    int wm   = wid >> 2, wn = wid & 3;        // warp grid 2(m) x 4(n)
    int n0   = blockIdx.x * 128;

    const char* gA = (const char*)Xfrag + (size_t)blockIdx.y * 24 * 8192;
    const char* gB = (const char*)Wfrag + (size_t)blockIdx.x * 24 * 8192;

    float d[4][4][4];
#pragma unroll
    for (int i = 0; i < 4; i++)
#pragma unroll
        for (int j = 0; j < 4; j++)
#pragma unroll
            for (int r = 0; r < 4; r++) d[i][j][r] = 0.f;

    // staging: one chunk64 = two contiguous 8KB chunk32 images per operand
    auto stage = [&](int c, uint32_t buf) {   // c in chunk64 units (0..11)
        size_t tb = (size_t)c * 16384;
#pragma unroll
        for (int p = 0; p < 4; p++) {
            uint32_t off = (uint32_t)(tid + p * 256) * 16;
            CP_ASYNC16(buf + SA_OFF + off, gA + tb + off);
            CP_ASYNC16(buf + SB_OFF + off, gB + tb + off);
        }
    };

    auto compute = [&](const char* buf) {
#pragma unroll
        for (int half = 0; half < 2; half++) {
            const char* Ab = buf + SA_OFF + half * 8192;
            const char* Bb = buf + SB_OFF + half * 8192;
#pragma unroll
            for (int ks = 0; ks < 2; ks++) {
                uint32_t a[4][4], b[4][2];
#pragma unroll
                for (int mt = 0; mt < 4; mt++) {
                    uint32_t aoff = (((wm * 4 + mt) * 2 + ks) * 32 + lane) * 16;
                    uint4 v = *(const uint4*)(Ab + aoff);
                    a[mt][0] = v.x; a[mt][1] = v.y; a[mt][2] = v.z; a[mt][3] = v.w;
                }
                // paired B: one LDS.128 per ntp = two n-tiles
#pragma unroll
                for (int ntp = 0; ntp < 2; ntp++) {
                    uint32_t boff = (((wn * 2 + ntp) * 2 + ks) * 32 + lane) * 16;
                    uint4 v = *(const uint4*)(Bb + boff);
                    b[2 * ntp][0]     = v.x; b[2 * ntp][1]     = v.y;
                    b[2 * ntp + 1][0] = v.z; b[2 * ntp + 1][1] = v.w;
                }
#pragma unroll
                for (int mt = 0; mt < 4; mt++)
#pragma unroll
                    for (int nt = 0; nt < 4; nt++)
                        mma_f16(d[mt][nt], a[mt], b[nt]);
            }
        }
    };

    // ---- prologue: stages 0 and 1 in flight ----
    stage(0, sbu);
    CP_COMMIT();
    stage(1, sbu + BUFSZ);
    CP_COMMIT();

    // ---- mainloop: 12 chunk64s, 3-stage pipeline, compile-time stage idx ----
    for (int cb = 0; cb < 12; cb += 3) {
#pragma unroll
        for (int j = 0; j < 3; j++) {
            int c = cb + j;
            if (c == 11) CP_WAIT0(); else CP_WAIT1();   // oldest group (c) done
            __syncthreads();
            compute(smb + j * BUFSZ);
            if (c + 2 < 12) {
                stage(c + 2, sbu + ((j + 2) % 3) * BUFSZ);
                CP_COMMIT();
            }
        }
    }

    // ---- fused epilogue: partial logit = sum_n tanh(z + b) * w ----
    int q = lane & 3, g = lane >> 2;
    float bv[4][2], wv[4][2];
#pragma unroll
    for (int nt = 0; nt < 4; nt++)
#pragma unroll
        for (int c = 0; c < 2; c++) {
            int n = n0 + wn * 32 + nt * 8 + 2 * q + c;
            bv[nt][c] = b_attn[n];
            wv[nt][c] = w_ctx[n];
        }

    int slice = blockIdx.x * 4 + wn;
    int m0 = blockIdx.y * 128;
#pragma unroll
    for (int mt = 0; mt < 4; mt++) {
        float s0 = 0.f, s1 = 0.f;
#pragma unroll
        for (int nt = 0; nt < 4; nt++)
#pragma unroll
            for (int c = 0; c < 2; c++) {
                s0 += tanh_fast(d[mt][nt][c]     + bv[nt][c]) * wv[nt][c];
                s1 += tanh_fast(d[mt][nt][2 + c] + bv[nt][c]) * wv[nt][c];
            }
        s0 += __shfl_xor_sync(0xffffffffu, s0, 1);
        s0 += __shfl_xor_sync(0xffffffffu, s0, 2);
        s1 += __shfl_xor_sync(0xffffffffu, s1, 1);
        s1 += __shfl_xor_sync(0xffffffffu, s1, 2);
        if (q == 0) {
            int mg = m0 + wm * 64 + mt * 16 + g;
            g_part[slice * M_ + mg]     = s0;
            g_part[slice * M_ + mg + 8] = s1;
        }
    }
}

// ---------------------------------------------------------------------------
// Kernel 3a: softmax weights a[b,s] from 24 partial-logit slices
// ---------------------------------------------------------------------------
__global__ __launch_bounds__(256) void attn_weights_kernel() {
    int b = blockIdx.x, t = threadIdx.x;
    __shared__ float lg[S_];
    __shared__ float red[256];

    for (int s = t; s < S_; s += 256) {
        float v = 0.f;
#pragma unroll
        for (int nt = 0; nt < NT_; nt++) v += g_part[nt * M_ + b * S_ + s];
        lg[s] = v;
    }
    __syncthreads();

    float mx = fmaxf(lg[t], lg[t + 256]);
    red[t] = mx;
    __syncthreads();
    for (int o = 128; o > 0; o >>= 1) {
        if (t < o) red[t] = fmaxf(red[t], red[t + o]);
        __syncthreads();
    }
    mx = red[0];
    __syncthreads();

    float e0 = __expf(lg[t] - mx);
    float e1 = __expf(lg[t + 256] - mx);
    red[t] = e0 + e1;
    __syncthreads();
    for (int o = 128; o > 0; o >>= 1) {
        if (t < o) red[t] += red[t + o];
        __syncthreads();
    }
    float inv = 1.0f / red[0];

    g_attn[b * S_ + t]       = e0 * inv;
    g_attn[b * S_ + t + 256] = e1 * inv;
}

// ---------------------------------------------------------------------------
// Kernel 3b: partial weighted sums
// ---------------------------------------------------------------------------
__global__ __launch_bounds__(128) void wsum_partial_kernel(
    const float* __restrict__ X) {
    int b = blockIdx.x, hc = blockIdx.y, sc = blockIdx.z;
    int t = threadIdx.x;
    int h = hc * 128 + t;

    const float* Xp = X + (size_t)b * S_ * H_ + (size_t)sc * 64 * H_ + h;
    const float* ap = g_attn + b * S_ + sc * 64;

    float acc = 0.f;
#pragma unroll 8
    for (int s = 0; s < 64; s++)
        acc = fmaf(ap[s], Xp[(size_t)s * H_], acc);

    g_sacc[(((b * 6) + hc) * 8 + sc) * 128 + t] = acc;
}

// ---------------------------------------------------------------------------
// Kernel 3c: reduce 8 s-chunk partials -> sent_repr
// ---------------------------------------------------------------------------
__global__ __launch_bounds__(128) void wsum_reduce_kernel(float* __restrict__ sent) {
    int b = blockIdx.x, hc = blockIdx.y, t = threadIdx.x;
    const float* p = g_sacc + (((b * 6) + hc) * 8) * 128 + t;
    float acc = 0.f;
#pragma unroll
    for (int sc = 0; sc < 8; sc++) acc += p[sc * 128];
    sent[b * H_ + hc * 128 + t] = acc;
}

// ---------------------------------------------------------------------------
// launch
// ---------------------------------------------------------------------------
extern "C" void kernel_launch(void* const* d_in, const int* in_sizes, int n_in,
                              void* d_out, int out_size) {
    const float* X       = (const float*)d_in[0];
    const int* segments  = (const int*)d_in[1];
    const int* smask     = (const int*)d_in[2];
    const int* imask     = (const int*)d_in[3];
    const float* W       = (const float*)d_in[4];
    const float* b_attn  = (const float*)d_in[5];
    const float* w_ctx   = (const float*)d_in[6];

    float* out_vectors = (float*)d_out;
    float* sent        = (float*)d_out + (size_t)B_ * MS_ * H_;

    cudaFuncSetAttribute(gemm_mma_kernel,
                         cudaFuncAttributeMaxDynamicSharedMemorySize, SM_REQ);

    split_fm_kernel<<<dim3(24, 134), 256>>>(X, W);
    gather_max_kernel<<<B_ * MS_, 192>>>(X, segments, smask, imask, out_vectors);
    gemm_mma_kernel<<<dim3(6, 128), 256, SM_REQ>>>(b_attn, w_ctx);
    attn_weights_kernel<<<B_, 256>>>();
    wsum_partial_kernel<<<dim3(B_, 6, 8), 128>>>(X);
    wsum_reduce_kernel<<<dim3(B_, 6), 128>>>(sent);
}

// round 13
// speedup vs baseline: 5.2935x; 1.0295x over previous
#include <cuda_runtime.h>
#include <cuda_fp16.h>
#include <cstdint>

// Problem sizes (fixed by the dataset)
#define B_  32
#define S_  512
#define H_  768
#define MS_ 128
#define SL_ 8
#define M_  (B_ * S_)        // 16384 rows of X
#define NT_ 6                // partial-logit slices (one per n-block)

#define NEG_INF -1e30f

// Scratch (device globals: no allocation allowed)
__device__ float g_part[NT_ * M_];                 // partial logits per n-slice
__device__ float g_attn[M_];                       // softmax weights a[b,s]
__device__ float g_sacc[B_ * 6 * 8 * 128];         // weighted-sum partials
// Fragment-major tiles: per (tile, chunk32) 2048 words (8KB), fp16.
__device__ uint4 Xfrag[M_ * H_ / 8];
__device__ uint4 Wfrag[H_ * H_ / 8];

// ---------------------------------------------------------------------------
// helpers
// ---------------------------------------------------------------------------
__device__ __forceinline__ uint32_t smem_u32(const void* p) {
    uint32_t a;
    asm("{ .reg .u64 t; cvta.to.shared.u64 t, %1; cvt.u32.u64 %0, t; }"
        : "=r"(a) : "l"(p));
    return a;
}

#define CP_ASYNC16(dst, src) \
    asm volatile("cp.async.cg.shared.global [%0], [%1], 16;" :: "r"(dst), "l"(src))
#define CP_COMMIT() asm volatile("cp.async.commit_group;" ::: "memory")
#define CP_WAIT0()  asm volatile("cp.async.wait_group 0;" ::: "memory")
#define CP_WAIT1()  asm volatile("cp.async.wait_group 1;" ::: "memory")

__device__ __forceinline__ void mma_f16(float* d, const uint32_t* a, const uint32_t* b) {
    asm volatile("mma.sync.aligned.m16n8k16.row.col.f32.f16.f16.f32 "
        "{%0,%1,%2,%3}, {%4,%5,%6,%7}, {%8,%9}, {%0,%1,%2,%3};"
        : "+f"(d[0]), "+f"(d[1]), "+f"(d[2]), "+f"(d[3])
        : "r"(a[0]), "r"(a[1]), "r"(a[2]), "r"(a[3]), "r"(b[0]), "r"(b[1]));
}

// fast tanh: tanh(x) = 1 - 2/(exp(2x)+1). 2 MUFU, abs err ~1e-6.
__device__ __forceinline__ float tanh_fast(float x) {
    float e = __expf(2.0f * x);
    return 1.0f - __fdividef(2.0f, e + 1.0f);
}

// pack two fp32 -> fp16x2 word
__device__ __forceinline__ uint32_t pack_h2(float x0, float x1) {
    __half h0 = __float2half_rn(x0);
    __half h1 = __float2half_rn(x1);
    return (uint32_t)__half_as_ushort(h0) | ((uint32_t)__half_as_ushort(h1) << 16);
}

// ---------------------------------------------------------------------------
// Fragment word layouts (word index within an 8KB chunk32 tile of 2048 words)
//   A tile: 128m x 32k.  W = ((mt*2+ks)*32 + lane)*4 + r
//   B tile: 128n x 32k, PAIRED: W = ((ntp*2+ks)*32 + lane)*4 + sub*2 + r
//     (ntp=nt>>1, sub=nt&1) — one LDS.128 feeds two adjacent n-tiles.
// ---------------------------------------------------------------------------

// Kernel 0: fused prepass + gather. 1D grid:
//   bid < 24*128         : X -> Xfrag (c = bid%24, mb = bid/24)
//   bid < 24*134         : W -> Wfrag (paired-B layout)
//   else                 : gather_max for segment bm = bid - 24*134
#define XSPLIT_BLOCKS (24 * 128)
#define SPLIT_BLOCKS  (24 * 134)
#define PREP_BLOCKS   (SPLIT_BLOCKS + B_ * MS_)

__global__ __launch_bounds__(256) void prep_kernel(
    const float* __restrict__ X, const float* __restrict__ W,
    const int* __restrict__ segments, const int* __restrict__ seg_mask,
    const int* __restrict__ idx_mask, float* __restrict__ out) {

    __shared__ float sbuf[4224];
    int bid = blockIdx.x;
    int t = threadIdx.x;

    if (bid < XSPLIT_BLOCKS) {
        int c = bid % 24, mb = bid / 24;
        float (*sX)[33] = (float (*)[33])sbuf;   // [128][33]
#pragma unroll
        for (int i = 0; i < 16; i++) {
            int idx = t + i * 256;  // 0..4095
            int m = idx >> 5, k = idx & 31;
            sX[m][k] = X[(size_t)(mb * 128 + m) * H_ + c * 32 + k];
        }
        __syncthreads();

        uint32_t* oh = (uint32_t*)Xfrag + ((size_t)mb * 24 + c) * 2048;
#pragma unroll
        for (int p = 0; p < 8; p++) {
            int w = t + p * 256;    // 0..2047
            int r = w & 3, lane = (w >> 2) & 31, g = w >> 7;   // g = mt*2+ks
            int mt = g >> 1, ks = g & 1;
            int m  = mt * 16 + ((r & 1) << 3) + (lane >> 2);
            int kp = ks * 8 + ((r >> 1) << 2) + (lane & 3);
            oh[w] = pack_h2(sX[m][2 * kp], sX[m][2 * kp + 1]);
        }
    } else if (bid < SPLIT_BLOCKS) {
        int bid2 = bid - XSPLIT_BLOCKS;
        int c = bid2 % 24, nb = bid2 / 24;
        float (*sW)[129] = (float (*)[129])sbuf; // [32][129]
#pragma unroll
        for (int i = 0; i < 16; i++) {
            int idx = t + i * 256;  // 0..4095
            int k = idx >> 7, n = idx & 127;
            sW[k][n] = W[(size_t)(c * 32 + k) * H_ + nb * 128 + n];
        }
        __syncthreads();

        uint32_t* oh = (uint32_t*)Wfrag + ((size_t)nb * 24 + c) * 2048;
#pragma unroll
        for (int p = 0; p < 8; p++) {
            int w = t + p * 256;
            int r2 = w & 3, lane = (w >> 2) & 31, g = w >> 7;  // g = ntp*2+ks
            int sub = r2 >> 1, r = r2 & 1;
            int ntp = g >> 1, ks = g & 1;
            int nt = ntp * 2 + sub;
            int n  = nt * 8 + (lane >> 2);
            int kp = ks * 8 + (r << 2) + (lane & 3);
            oh[w] = pack_h2(sW[2 * kp][n], sW[2 * kp + 1][n]);
        }
    } else {
        // gather_max: one segment per block, 192 active threads
        int bm = bid - SPLIT_BLOCKS;
        int b  = bm >> 7;
        int* sidx   = (int*)sbuf;
        int* svalid = (int*)sbuf + SL_;
        if (t < SL_) {
            sidx[t]   = segments[bm * SL_ + t];
            svalid[t] = idx_mask[bm * SL_ + t];
        }
        __syncthreads();
        if (t < 192) {
            const float4* Xb = (const float4*)(X + (size_t)b * S_ * H_);
            bool ok = seg_mask[bm] != 0;
            float4 r;
            if (!ok) {
                r = Xb[(size_t)(S_ - 2) * (H_ / 4) + t];
            } else {
                r = make_float4(NEG_INF, NEG_INF, NEG_INF, NEG_INF);
#pragma unroll
                for (int sl = 0; sl < SL_; sl++) {
                    if (svalid[sl]) {
                        float4 v = Xb[(size_t)sidx[sl] * (H_ / 4) + t];
                        r.x = fmaxf(r.x, v.x);
                        r.y = fmaxf(r.y, v.y);
                        r.z = fmaxf(r.z, v.z);
                        r.w = fmaxf(r.w, v.w);
                    }
                }
            }
            ((float4*)out)[(size_t)bm * (H_ / 4) + t] = r;
        }
    }
}

// ---------------------------------------------------------------------------
// Kernel 2: plain fp16 mma.sync GEMM + fused tanh/w_ctx epilogue
//   z = fp16(A) * fp16(W), fp32 accumulate, paired-B LDS.128 feeds
//   grid (6 n-blocks, 128 m-tiles), 256 threads (8 warps, warp tile 64x32)
//   BM=128 BN=128 BK=64 (two chunk32 images per stage), 12 iterations,
//   3-stage cp.async pipeline; epilogue reduces across wn warps in SMEM
//   so each CTA emits ONE slice (NT=6).
// ---------------------------------------------------------------------------
#define SA_OFF 0
#define SB_OFF 16384
#define BUFSZ 32768
#define STAGES 3
#define SM_REQ (STAGES * BUFSZ)

__global__ __launch_bounds__(256, 2) void gemm_mma_kernel(
    const float* __restrict__ b_attn, const float* __restrict__ w_ctx) {

    extern __shared__ __align__(128) char smb[];
    uint32_t sbu = smem_u32(smb);

    int tid  = threadIdx.x;
    int wid  = tid >> 5, lane = tid & 31;
    int wm   = wid >> 2, wn = wid & 3;        // warp grid 2(m) x 4(n)
    int n0   = blockIdx.x * 128;

    const char* gA = (const char*)Xfrag + (size_t)blockIdx.y * 24 * 8192;
    const char* gB = (const char*)Wfrag + (size_t)blockIdx.x * 24 * 8192;

    float d[4][4][4];
#pragma unroll
    for (int i = 0; i < 4; i++)
#pragma unroll
        for (int j = 0; j < 4; j++)
#pragma unroll
            for (int r = 0; r < 4; r++) d[i][j][r] = 0.f;

    // staging: one chunk64 = two contiguous 8KB chunk32 images per operand
    auto stage = [&](int c, uint32_t buf) {   // c in chunk64 units (0..11)
        size_t tb = (size_t)c * 16384;
#pragma unroll
        for (int p = 0; p < 4; p++) {
            uint32_t off = (uint32_t)(tid + p * 256) * 16;
            CP_ASYNC16(buf + SA_OFF + off, gA + tb + off);
            CP_ASYNC16(buf + SB_OFF + off, gB + tb + off);
        }
    };

    auto compute = [&](const char* buf) {
#pragma unroll
        for (int half = 0; half < 2; half++) {
            const char* Ab = buf + SA_OFF + half * 8192;
            const char* Bb = buf + SB_OFF + half * 8192;
#pragma unroll
            for (int ks = 0; ks < 2; ks++) {
                uint32_t a[4][4], b[4][2];
#pragma unroll
                for (int mt = 0; mt < 4; mt++) {
                    uint32_t aoff = (((wm * 4 + mt) * 2 + ks) * 32 + lane) * 16;
                    uint4 v = *(const uint4*)(Ab + aoff);
                    a[mt][0] = v.x; a[mt][1] = v.y; a[mt][2] = v.z; a[mt][3] = v.w;
                }
                // paired B: one LDS.128 per ntp = two n-tiles
#pragma unroll
                for (int ntp = 0; ntp < 2; ntp++) {
                    uint32_t boff = (((wn * 2 + ntp) * 2 + ks) * 32 + lane) * 16;
                    uint4 v = *(const uint4*)(Bb + boff);
                    b[2 * ntp][0]     = v.x; b[2 * ntp][1]     = v.y;
                    b[2 * ntp + 1][0] = v.z; b[2 * ntp + 1][1] = v.w;
                }
#pragma unroll
                for (int mt = 0; mt < 4; mt++)
#pragma unroll
                    for (int nt = 0; nt < 4; nt++)
                        mma_f16(d[mt][nt], a[mt], b[nt]);
            }
        }
    };

    // ---- prologue: stages 0 and 1 in flight ----
    stage(0, sbu);
    CP_COMMIT();
    stage(1, sbu + BUFSZ);
    CP_COMMIT();

    // ---- mainloop: 12 chunk64s, 3-stage pipeline, compile-time stage idx ----
    for (int cb = 0; cb < 12; cb += 3) {
#pragma unroll
        for (int j = 0; j < 3; j++) {
            int c = cb + j;
            if (c == 11) CP_WAIT0(); else CP_WAIT1();   // oldest group (c) done
            __syncthreads();
            compute(smb + j * BUFSZ);
            if (c + 2 < 12) {
                stage(c + 2, sbu + ((j + 2) % 3) * BUFSZ);
                CP_COMMIT();
            }
        }
    }

    // ---- fused epilogue: tanh + dot(w_ctx), reduce across q lanes (shfl)
    //      then across the 4 wn warps (SMEM) -> one slice per CTA ----
    __syncthreads();                      // done reading stage SMEM
    float* sred = (float*)smb;            // [4][128] floats, 2KB

    int q = lane & 3, g = lane >> 2;
    float bv[4][2], wv[4][2];
#pragma unroll
    for (int nt = 0; nt < 4; nt++)
#pragma unroll
        for (int c = 0; c < 2; c++) {
            int n = n0 + wn * 32 + nt * 8 + 2 * q + c;
            bv[nt][c] = b_attn[n];
            wv[nt][c] = w_ctx[n];
        }

#pragma unroll
    for (int mt = 0; mt < 4; mt++) {
        float s0 = 0.f, s1 = 0.f;
#pragma unroll
        for (int nt = 0; nt < 4; nt++)
#pragma unroll
            for (int c = 0; c < 2; c++) {
                s0 += tanh_fast(d[mt][nt][c]     + bv[nt][c]) * wv[nt][c];
                s1 += tanh_fast(d[mt][nt][2 + c] + bv[nt][c]) * wv[nt][c];
            }
        s0 += __shfl_xor_sync(0xffffffffu, s0, 1);
        s0 += __shfl_xor_sync(0xffffffffu, s0, 2);
        s1 += __shfl_xor_sync(0xffffffffu, s1, 1);
        s1 += __shfl_xor_sync(0xffffffffu, s1, 2);
        if (q == 0) {
            int ml = wm * 64 + mt * 16 + g;
            sred[wn * 128 + ml]     = s0;
            sred[wn * 128 + ml + 8] = s1;
        }
    }
    __syncthreads();

    if (tid < 128) {
        float v = sred[tid] + sred[128 + tid] + sred[256 + tid] + sred[384 + tid];
        g_part[blockIdx.x * M_ + blockIdx.y * 128 + tid] = v;
    }
}

// ---------------------------------------------------------------------------
// Kernel 3a: softmax weights a[b,s] from 6 partial-logit slices
// ---------------------------------------------------------------------------
__global__ __launch_bounds__(256) void attn_weights_kernel() {
    int b = blockIdx.x, t = threadIdx.x;
    __shared__ float lg[S_];
    __shared__ float red[256];

    for (int s = t; s < S_; s += 256) {
        float v = 0.f;
#pragma unroll
        for (int nt = 0; nt < NT_; nt++) v += g_part[nt * M_ + b * S_ + s];
        lg[s] = v;
    }
    __syncthreads();

    float mx = fmaxf(lg[t], lg[t + 256]);
    red[t] = mx;
    __syncthreads();
    for (int o = 128; o > 0; o >>= 1) {
        if (t < o) red[t] = fmaxf(red[t], red[t + o]);
        __syncthreads();
    }
    mx = red[0];
    __syncthreads();

    float e0 = __expf(lg[t] - mx);
    float e1 = __expf(lg[t + 256] - mx);
    red[t] = e0 + e1;
    __syncthreads();
    for (int o = 128; o > 0; o >>= 1) {
        if (t < o) red[t] += red[t + o];
        __syncthreads();
    }
    float inv = 1.0f / red[0];

    g_attn[b * S_ + t]       = e0 * inv;
    g_attn[b * S_ + t + 256] = e1 * inv;
}

// ---------------------------------------------------------------------------
// Kernel 3b: partial weighted sums
// ---------------------------------------------------------------------------
__global__ __launch_bounds__(128) void wsum_partial_kernel(
    const float* __restrict__ X) {
    int b = blockIdx.x, hc = blockIdx.y, sc = blockIdx.z;
    int t = threadIdx.x;
    int h = hc * 128 + t;

    const float* Xp = X + (size_t)b * S_ * H_ + (size_t)sc * 64 * H_ + h;
    const float* ap = g_attn + b * S_ + sc * 64;

    float acc = 0.f;
#pragma unroll 8
    for (int s = 0; s < 64; s++)
        acc = fmaf(ap[s], Xp[(size_t)s * H_], acc);

    g_sacc[(((b * 6) + hc) * 8 + sc) * 128 + t] = acc;
}

// ---------------------------------------------------------------------------
// Kernel 3c: reduce 8 s-chunk partials -> sent_repr
// ---------------------------------------------------------------------------
__global__ __launch_bounds__(128) void wsum_reduce_kernel(float* __restrict__ sent) {
    int b = blockIdx.x, hc = blockIdx.y, t = threadIdx.x;
    const float* p = g_sacc + (((b * 6) + hc) * 8) * 128 + t;
    float acc = 0.f;
#pragma unroll
    for (int sc = 0; sc < 8; sc++) acc += p[sc * 128];
    sent[b * H_ + hc * 128 + t] = acc;
}

// ---------------------------------------------------------------------------
// launch
// ---------------------------------------------------------------------------
extern "C" void kernel_launch(void* const* d_in, const int* in_sizes, int n_in,
                              void* d_out, int out_size) {
    const float* X       = (const float*)d_in[0];
    const int* segments  = (const int*)d_in[1];
    const int* smask     = (const int*)d_in[2];
    const int* imask     = (const int*)d_in[3];
    const float* W       = (const float*)d_in[4];
    const float* b_attn  = (const float*)d_in[5];
    const float* w_ctx   = (const float*)d_in[6];

    float* out_vectors = (float*)d_out;
    float* sent        = (float*)d_out + (size_t)B_ * MS_ * H_;

    cudaFuncSetAttribute(gemm_mma_kernel,
                         cudaFuncAttributeMaxDynamicSharedMemorySize, SM_REQ);

    prep_kernel<<<PREP_BLOCKS, 256>>>(X, W, segments, smask, imask, out_vectors);
    gemm_mma_kernel<<<dim3(6, 128), 256, SM_REQ>>>(b_attn, w_ctx);
    attn_weights_kernel<<<B_, 256>>>();
    wsum_partial_kernel<<<dim3(B_, 6, 8), 128>>>(X);
    wsum_reduce_kernel<<<dim3(B_, 6), 128>>>(sent);
}

// round 14
// speedup vs baseline: 5.4138x; 1.0227x over previous
#include <cuda_runtime.h>
#include <cuda_fp16.h>
#include <cstdint>

// Problem sizes (fixed by the dataset)
#define B_  32
#define S_  512
#define H_  768
#define MS_ 128
#define SL_ 8
#define M_  (B_ * S_)        // 16384 rows of X
#define NT_ 6                // partial-logit slices (one per n-block)

#define NEG_INF -1e30f

// Scratch (device globals: no allocation allowed)
__device__ float g_part[NT_ * M_];                 // partial logits per n-slice
__device__ float g_attn[M_];                       // softmax weights a[b,s]
__device__ float g_sacc[B_ * 6 * 16 * 128];        // weighted-sum partials
// Fragment-major tiles: per (tile, chunk32) 2048 words (8KB), fp16.
__device__ uint4 Xfrag[M_ * H_ / 8];
__device__ uint4 Wfrag[H_ * H_ / 8];

// ---------------------------------------------------------------------------
// helpers
// ---------------------------------------------------------------------------
__device__ __forceinline__ uint32_t smem_u32(const void* p) {
    uint32_t a;
    asm("{ .reg .u64 t; cvta.to.shared.u64 t, %1; cvt.u32.u64 %0, t; }"
        : "=r"(a) : "l"(p));
    return a;
}

#define CP_ASYNC16(dst, src) \
    asm volatile("cp.async.cg.shared.global [%0], [%1], 16;" :: "r"(dst), "l"(src))
#define CP_COMMIT() asm volatile("cp.async.commit_group;" ::: "memory")
#define CP_WAIT0()  asm volatile("cp.async.wait_group 0;" ::: "memory")
#define CP_WAIT1()  asm volatile("cp.async.wait_group 1;" ::: "memory")

__device__ __forceinline__ void mma_f16(float* d, const uint32_t* a, const uint32_t* b) {
    asm volatile("mma.sync.aligned.m16n8k16.row.col.f32.f16.f16.f32 "
        "{%0,%1,%2,%3}, {%4,%5,%6,%7}, {%8,%9}, {%0,%1,%2,%3};"
        : "+f"(d[0]), "+f"(d[1]), "+f"(d[2]), "+f"(d[3])
        : "r"(a[0]), "r"(a[1]), "r"(a[2]), "r"(a[3]), "r"(b[0]), "r"(b[1]));
}

// fast tanh: tanh(x) = 1 - 2/(exp(2x)+1). 2 MUFU, abs err ~1e-6.
__device__ __forceinline__ float tanh_fast(float x) {
    float e = __expf(2.0f * x);
    return 1.0f - __fdividef(2.0f, e + 1.0f);
}

// pack two fp32 -> fp16x2 word
__device__ __forceinline__ uint32_t pack_h2(float x0, float x1) {
    __half h0 = __float2half_rn(x0);
    __half h1 = __float2half_rn(x1);
    return (uint32_t)__half_as_ushort(h0) | ((uint32_t)__half_as_ushort(h1) << 16);
}

// ---------------------------------------------------------------------------
// Fragment word layouts (word index within an 8KB chunk32 tile of 2048 words)
//   A tile: 128m x 32k.  W = ((mt*2+ks)*32 + lane)*4 + r
//   B tile: 128n x 32k, PAIRED: W = ((ntp*2+ks)*32 + lane)*4 + sub*2 + r
//     (ntp=nt>>1, sub=nt&1) — one LDS.128 feeds two adjacent n-tiles.
// ---------------------------------------------------------------------------

// Kernel 0: fused prepass + gather. 1D grid:
//   bid < 24*128         : X -> Xfrag (c = bid%24, mb = bid/24)
//   bid < 24*134         : W -> Wfrag (paired-B layout)
//   else                 : gather_max for segment bm = bid - 24*134
#define XSPLIT_BLOCKS (24 * 128)
#define SPLIT_BLOCKS  (24 * 134)
#define PREP_BLOCKS   (SPLIT_BLOCKS + B_ * MS_)

__global__ __launch_bounds__(256) void prep_kernel(
    const float* __restrict__ X, const float* __restrict__ W,
    const int* __restrict__ segments, const int* __restrict__ seg_mask,
    const int* __restrict__ idx_mask, float* __restrict__ out) {

    __shared__ float sbuf[4224];
    int bid = blockIdx.x;
    int t = threadIdx.x;

    if (bid < XSPLIT_BLOCKS) {
        int c = bid % 24, mb = bid / 24;
        float (*sX)[33] = (float (*)[33])sbuf;   // [128][33]
#pragma unroll
        for (int i = 0; i < 16; i++) {
            int idx = t + i * 256;  // 0..4095
            int m = idx >> 5, k = idx & 31;
            sX[m][k] = X[(size_t)(mb * 128 + m) * H_ + c * 32 + k];
        }
        __syncthreads();

        uint32_t* oh = (uint32_t*)Xfrag + ((size_t)mb * 24 + c) * 2048;
#pragma unroll
        for (int p = 0; p < 8; p++) {
            int w = t + p * 256;    // 0..2047
            int r = w & 3, lane = (w >> 2) & 31, g = w >> 7;   // g = mt*2+ks
            int mt = g >> 1, ks = g & 1;
            int m  = mt * 16 + ((r & 1) << 3) + (lane >> 2);
            int kp = ks * 8 + ((r >> 1) << 2) + (lane & 3);
            oh[w] = pack_h2(sX[m][2 * kp], sX[m][2 * kp + 1]);
        }
    } else if (bid < SPLIT_BLOCKS) {
        int bid2 = bid - XSPLIT_BLOCKS;
        int c = bid2 % 24, nb = bid2 / 24;
        float (*sW)[129] = (float (*)[129])sbuf; // [32][129]
#pragma unroll
        for (int i = 0; i < 16; i++) {
            int idx = t + i * 256;  // 0..4095
            int k = idx >> 7, n = idx & 127;
            sW[k][n] = W[(size_t)(c * 32 + k) * H_ + nb * 128 + n];
        }
        __syncthreads();

        uint32_t* oh = (uint32_t*)Wfrag + ((size_t)nb * 24 + c) * 2048;
#pragma unroll
        for (int p = 0; p < 8; p++) {
            int w = t + p * 256;
            int r2 = w & 3, lane = (w >> 2) & 31, g = w >> 7;  // g = ntp*2+ks
            int sub = r2 >> 1, r = r2 & 1;
            int ntp = g >> 1, ks = g & 1;
            int nt = ntp * 2 + sub;
            int n  = nt * 8 + (lane >> 2);
            int kp = ks * 8 + (r << 2) + (lane & 3);
            oh[w] = pack_h2(sW[2 * kp][n], sW[2 * kp + 1][n]);
        }
    } else {
        // gather_max: one segment per block, 192 active threads
        int bm = bid - SPLIT_BLOCKS;
        int b  = bm >> 7;
        int* sidx   = (int*)sbuf;
        int* svalid = (int*)sbuf + SL_;
        if (t < SL_) {
            sidx[t]   = segments[bm * SL_ + t];
            svalid[t] = idx_mask[bm * SL_ + t];
        }
        __syncthreads();
        if (t < 192) {
            const float4* Xb = (const float4*)(X + (size_t)b * S_ * H_);
            bool ok = seg_mask[bm] != 0;
            float4 r;
            if (!ok) {
                r = Xb[(size_t)(S_ - 2) * (H_ / 4) + t];
            } else {
                r = make_float4(NEG_INF, NEG_INF, NEG_INF, NEG_INF);
#pragma unroll
                for (int sl = 0; sl < SL_; sl++) {
                    if (svalid[sl]) {
                        float4 v = Xb[(size_t)sidx[sl] * (H_ / 4) + t];
                        r.x = fmaxf(r.x, v.x);
                        r.y = fmaxf(r.y, v.y);
                        r.z = fmaxf(r.z, v.z);
                        r.w = fmaxf(r.w, v.w);
                    }
                }
            }
            ((float4*)out)[(size_t)bm * (H_ / 4) + t] = r;
        }
    }
}

// ---------------------------------------------------------------------------
// Kernel 2: plain fp16 mma.sync GEMM + fused tanh/w_ctx epilogue
//   z = fp16(A) * fp16(W), fp32 accumulate, paired-B LDS.128 feeds
//   grid (6 n-blocks, 128 m-tiles), 256 threads (8 warps, warp tile 64x32)
//   BM=128 BN=128 BK=64 (two chunk32 images per stage), 12 iterations,
//   3-stage cp.async pipeline; epilogue reduces across wn warps in SMEM
//   so each CTA emits ONE slice (NT=6).
// ---------------------------------------------------------------------------
#define SA_OFF 0
#define SB_OFF 16384
#define BUFSZ 32768
#define STAGES 3
#define SM_REQ (STAGES * BUFSZ)

__global__ __launch_bounds__(256, 2) void gemm_mma_kernel(
    const float* __restrict__ b_attn, const float* __restrict__ w_ctx) {

    extern __shared__ __align__(128) char smb[];
    uint32_t sbu = smem_u32(smb);

    int tid  = threadIdx.x;
    int wid  = tid >> 5, lane = tid & 31;
    int wm   = wid >> 2, wn = wid & 3;        // warp grid 2(m) x 4(n)
    int n0   = blockIdx.x * 128;

    const char* gA = (const char*)Xfrag + (size_t)blockIdx.y * 24 * 8192;
    const char* gB = (const char*)Wfrag + (size_t)blockIdx.x * 24 * 8192;

    float d[4][4][4];
#pragma unroll
    for (int i = 0; i < 4; i++)
#pragma unroll
        for (int j = 0; j < 4; j++)
#pragma unroll
            for (int r = 0; r < 4; r++) d[i][j][r] = 0.f;

    // staging: one chunk64 = two contiguous 8KB chunk32 images per operand
    auto stage = [&](int c, uint32_t buf) {   // c in chunk64 units (0..11)
        size_t tb = (size_t)c * 16384;
#pragma unroll
        for (int p = 0; p < 4; p++) {
            uint32_t off = (uint32_t)(tid + p * 256) * 16;
            CP_ASYNC16(buf + SA_OFF + off, gA + tb + off);
            CP_ASYNC16(buf + SB_OFF + off, gB + tb + off);
        }
    };

    auto compute = [&](const char* buf) {
#pragma unroll
        for (int half = 0; half < 2; half++) {
            const char* Ab = buf + SA_OFF + half * 8192;
            const char* Bb = buf + SB_OFF + half * 8192;
#pragma unroll
            for (int ks = 0; ks < 2; ks++) {
                uint32_t a[4][4], b[4][2];
#pragma unroll
                for (int mt = 0; mt < 4; mt++) {
                    uint32_t aoff = (((wm * 4 + mt) * 2 + ks) * 32 + lane) * 16;
                    uint4 v = *(const uint4*)(Ab + aoff);
                    a[mt][0] = v.x; a[mt][1] = v.y; a[mt][2] = v.z; a[mt][3] = v.w;
                }
                // paired B: one LDS.128 per ntp = two n-tiles
#pragma unroll
                for (int ntp = 0; ntp < 2; ntp++) {
                    uint32_t boff = (((wn * 2 + ntp) * 2 + ks) * 32 + lane) * 16;
                    uint4 v = *(const uint4*)(Bb + boff);
                    b[2 * ntp][0]     = v.x; b[2 * ntp][1]     = v.y;
                    b[2 * ntp + 1][0] = v.z; b[2 * ntp + 1][1] = v.w;
                }
#pragma unroll
                for (int mt = 0; mt < 4; mt++)
#pragma unroll
                    for (int nt = 0; nt < 4; nt++)
                        mma_f16(d[mt][nt], a[mt], b[nt]);
            }
        }
    };

    // ---- prologue: stages 0 and 1 in flight ----
    stage(0, sbu);
    CP_COMMIT();
    stage(1, sbu + BUFSZ);
    CP_COMMIT();

    // ---- mainloop: 12 chunk64s, 3-stage pipeline, compile-time stage idx ----
    for (int cb = 0; cb < 12; cb += 3) {
#pragma unroll
        for (int j = 0; j < 3; j++) {
            int c = cb + j;
            if (c == 11) CP_WAIT0(); else CP_WAIT1();   // oldest group (c) done
            __syncthreads();
            compute(smb + j * BUFSZ);
            if (c + 2 < 12) {
                stage(c + 2, sbu + ((j + 2) % 3) * BUFSZ);
                CP_COMMIT();
            }
        }
    }

    // ---- fused epilogue: tanh + dot(w_ctx), reduce across q lanes (shfl)
    //      then across the 4 wn warps (SMEM) -> one slice per CTA ----
    __syncthreads();                      // done reading stage SMEM
    float* sred = (float*)smb;            // [4][128] floats, 2KB

    int q = lane & 3, g = lane >> 2;
    float bv[4][2], wv[4][2];
#pragma unroll
    for (int nt = 0; nt < 4; nt++)
#pragma unroll
        for (int c = 0; c < 2; c++) {
            int n = n0 + wn * 32 + nt * 8 + 2 * q + c;
            bv[nt][c] = b_attn[n];
            wv[nt][c] = w_ctx[n];
        }

#pragma unroll
    for (int mt = 0; mt < 4; mt++) {
        float s0 = 0.f, s1 = 0.f;
#pragma unroll
        for (int nt = 0; nt < 4; nt++)
#pragma unroll
            for (int c = 0; c < 2; c++) {
                s0 += tanh_fast(d[mt][nt][c]     + bv[nt][c]) * wv[nt][c];
                s1 += tanh_fast(d[mt][nt][2 + c] + bv[nt][c]) * wv[nt][c];
            }
        s0 += __shfl_xor_sync(0xffffffffu, s0, 1);
        s0 += __shfl_xor_sync(0xffffffffu, s0, 2);
        s1 += __shfl_xor_sync(0xffffffffu, s1, 1);
        s1 += __shfl_xor_sync(0xffffffffu, s1, 2);
        if (q == 0) {
            int ml = wm * 64 + mt * 16 + g;
            sred[wn * 128 + ml]     = s0;
            sred[wn * 128 + ml + 8] = s1;
        }
    }
    __syncthreads();

    if (tid < 128) {
        float v = sred[tid] + sred[128 + tid] + sred[256 + tid] + sred[384 + tid];
        g_part[blockIdx.x * M_ + blockIdx.y * 128 + tid] = v;
    }
}

// ---------------------------------------------------------------------------
// Kernel 3a: softmax weights a[b,s] from 6 partial-logit slices
// ---------------------------------------------------------------------------
__global__ __launch_bounds__(256) void attn_weights_kernel() {
    int b = blockIdx.x, t = threadIdx.x;
    __shared__ float lg[S_];
    __shared__ float red[256];

    for (int s = t; s < S_; s += 256) {
        float v = 0.f;
#pragma unroll
        for (int nt = 0; nt < NT_; nt++) v += g_part[nt * M_ + b * S_ + s];
        lg[s] = v;
    }
    __syncthreads();

    float mx = fmaxf(lg[t], lg[t + 256]);
    red[t] = mx;
    __syncthreads();
    for (int o = 128; o > 0; o >>= 1) {
        if (t < o) red[t] = fmaxf(red[t], red[t + o]);
        __syncthreads();
    }
    mx = red[0];
    __syncthreads();

    float e0 = __expf(lg[t] - mx);
    float e1 = __expf(lg[t + 256] - mx);
    red[t] = e0 + e1;
    __syncthreads();
    for (int o = 128; o > 0; o >>= 1) {
        if (t < o) red[t] += red[t + o];
        __syncthreads();
    }
    float inv = 1.0f / red[0];

    g_attn[b * S_ + t]       = e0 * inv;
    g_attn[b * S_ + t + 256] = e1 * inv;
}

// ---------------------------------------------------------------------------
// Kernel 3b: partial weighted sums — grid (B, 6 hc, 16 sc), 32 s each,
// fully unrolled for high MLP
// ---------------------------------------------------------------------------
__global__ __launch_bounds__(128) void wsum_partial_kernel(
    const float* __restrict__ X) {
    int b = blockIdx.x, hc = blockIdx.y, sc = blockIdx.z;
    int t = threadIdx.x;
    int h = hc * 128 + t;

    const float* Xp = X + (size_t)b * S_ * H_ + (size_t)sc * 32 * H_ + h;
    const float* ap = g_attn + b * S_ + sc * 32;

    float acc = 0.f;
#pragma unroll
    for (int s = 0; s < 32; s++)
        acc = fmaf(ap[s], Xp[(size_t)s * H_], acc);

    g_sacc[(((b * 6) + hc) * 16 + sc) * 128 + t] = acc;
}

// ---------------------------------------------------------------------------
// Kernel 3c: reduce 16 s-chunk partials -> sent_repr
// ---------------------------------------------------------------------------
__global__ __launch_bounds__(128) void wsum_reduce_kernel(float* __restrict__ sent) {
    int b = blockIdx.x, hc = blockIdx.y, t = threadIdx.x;
    const float* p = g_sacc + (((b * 6) + hc) * 16) * 128 + t;
    float acc = 0.f;
#pragma unroll
    for (int sc = 0; sc < 16; sc++) acc += p[sc * 128];
    sent[b * H_ + hc * 128 + t] = acc;
}

// ---------------------------------------------------------------------------
// launch
// ---------------------------------------------------------------------------
extern "C" void kernel_launch(void* const* d_in, const int* in_sizes, int n_in,
                              void* d_out, int out_size) {
    const float* X       = (const float*)d_in[0];
    const int* segments  = (const int*)d_in[1];
    const int* smask     = (const int*)d_in[2];
    const int* imask     = (const int*)d_in[3];
    const float* W       = (const float*)d_in[4];
    const float* b_attn  = (const float*)d_in[5];
    const float* w_ctx   = (const float*)d_in[6];

    float* out_vectors = (float*)d_out;
    float* sent        = (float*)d_out + (size_t)B_ * MS_ * H_;

    cudaFuncSetAttribute(gemm_mma_kernel,
                         cudaFuncAttributeMaxDynamicSharedMemorySize, SM_REQ);

    prep_kernel<<<PREP_BLOCKS, 256>>>(X, W, segments, smask, imask, out_vectors);
    gemm_mma_kernel<<<dim3(6, 128), 256, SM_REQ>>>(b_attn, w_ctx);
    attn_weights_kernel<<<B_, 256>>>();
    wsum_partial_kernel<<<dim3(B_, 6, 16), 128>>>(X);
    wsum_reduce_kernel<<<dim3(B_, 6), 128>>>(sent);
}